// round 1
// baseline (speedup 1.0000x reference)
#include <cuda_runtime.h>
#include <math.h>
#include <stddef.h>

#define D 512
#define LSEQ 1024
#define BATCH 8
#define NH 8
#define HD 64
#define ROWS (BATCH*LSEQ)   /* 8192  */
#define BH (BATCH*NH)       /* 64    */

// ---------------- scratch (no allocations allowed) ----------------
__device__ float g_q[ROWS*D];
__device__ float g_k[ROWS*D];
__device__ float g_v[ROWS*D];
__device__ float g_ctx[ROWS*D];
__device__ float g_proj[ROWS*D];
__device__ float g_hid[(size_t)2*ROWS*2*D];   // 16384 x 1024
__device__ float g_ffn[(size_t)2*ROWS*D];     // 16384 x 512

// ---------------- dense GEMM: C[M,N] = A[M,K] @ B[N,K]^T + bias, opt relu ----
// M,N multiples of 128; K multiple of 16.
__global__ void __launch_bounds__(256) gemm_tn(
    const float* __restrict__ A, const float* __restrict__ B,
    const float* __restrict__ bias, float* __restrict__ C,
    int M, int N, int K, int relu)
{
  __shared__ float As[16][128];
  __shared__ float Bs[16][128];
  const int bm = blockIdx.y * 128;
  const int bn = blockIdx.x * 128;
  const int tid = threadIdx.x;
  const int tx = tid & 15;
  const int ty = tid >> 4;
  float acc[8][8];
  #pragma unroll
  for (int i = 0; i < 8; i++)
    #pragma unroll
    for (int j = 0; j < 8; j++) acc[i][j] = 0.f;

  for (int k0 = 0; k0 < K; k0 += 16) {
    #pragma unroll
    for (int it = 0; it < 2; ++it) {
      int idx = tid + it * 256;       // 0..511 float4 slots
      int r   = idx >> 2;             // 0..127
      int c4  = (idx & 3) * 4;        // 0,4,8,12
      float4 va = *(const float4*)&A[(size_t)(bm + r) * K + k0 + c4];
      As[c4+0][r] = va.x; As[c4+1][r] = va.y; As[c4+2][r] = va.z; As[c4+3][r] = va.w;
      float4 vb = *(const float4*)&B[(size_t)(bn + r) * K + k0 + c4];
      Bs[c4+0][r] = vb.x; Bs[c4+1][r] = vb.y; Bs[c4+2][r] = vb.z; Bs[c4+3][r] = vb.w;
    }
    __syncthreads();
    #pragma unroll
    for (int k = 0; k < 16; k++) {
      float a[8], b[8];
      *(float4*)&a[0] = *(const float4*)&As[k][ty*8];
      *(float4*)&a[4] = *(const float4*)&As[k][ty*8+4];
      *(float4*)&b[0] = *(const float4*)&Bs[k][tx*8];
      *(float4*)&b[4] = *(const float4*)&Bs[k][tx*8+4];
      #pragma unroll
      for (int i = 0; i < 8; i++)
        #pragma unroll
        for (int j = 0; j < 8; j++)
          acc[i][j] = fmaf(a[i], b[j], acc[i][j]);
    }
    __syncthreads();
  }
  #pragma unroll
  for (int i = 0; i < 8; i++) {
    const int row = bm + ty*8 + i;
    #pragma unroll
    for (int j = 0; j < 8; j++) {
      int col = bn + tx*8 + j;
      float v = acc[i][j] + bias[col];
      if (relu) v = fmaxf(v, 0.f);
      C[(size_t)row * N + col] = v;
    }
  }
}

// ---------------- scores: attn[z,l,s] = (Q[b,l,h,:] . K[b,s,h,:]) / 8 ----------
// grid (16 s-tiles, 16 l-tiles, 64 bh), 64x64 tile, K=64 fully resident.
__global__ void __launch_bounds__(256) scores_kernel(
    const float* __restrict__ Q, const float* __restrict__ K,
    float* __restrict__ attn)
{
  const int z = blockIdx.z;
  const int b = z >> 3, h = z & 7;
  const int l0 = blockIdx.y * 64;
  const int s0 = blockIdx.x * 64;
  const float* Qb = Q + (size_t)b * LSEQ * D + h * HD;
  const float* Kb = K + (size_t)b * LSEQ * D + h * HD;
  float* Cb = attn + (size_t)z * LSEQ * LSEQ;
  __shared__ float Qs[64][65];   // [k][l]
  __shared__ float Ks[64][65];   // [k][s]
  const int tid = threadIdx.x;
  const int tx = tid & 15, ty = tid >> 4;
  #pragma unroll
  for (int it = 0; it < 4; ++it) {
    int idx = tid + it * 256;     // 0..1023 float4 slots
    int r   = idx >> 4;           // row within tile
    int c4  = (idx & 15) * 4;     // k offset
    float4 vq = *(const float4*)&Qb[(size_t)(l0 + r) * D + c4];
    Qs[c4+0][r] = vq.x; Qs[c4+1][r] = vq.y; Qs[c4+2][r] = vq.z; Qs[c4+3][r] = vq.w;
    float4 vk = *(const float4*)&Kb[(size_t)(s0 + r) * D + c4];
    Ks[c4+0][r] = vk.x; Ks[c4+1][r] = vk.y; Ks[c4+2][r] = vk.z; Ks[c4+3][r] = vk.w;
  }
  __syncthreads();
  float acc[4][4] = {};
  #pragma unroll
  for (int k = 0; k < 64; k++) {
    float a[4], b4[4];
    #pragma unroll
    for (int i = 0; i < 4; i++) a[i]  = Qs[k][ty*4 + i];
    #pragma unroll
    for (int j = 0; j < 4; j++) b4[j] = Ks[k][tx*4 + j];
    #pragma unroll
    for (int i = 0; i < 4; i++)
      #pragma unroll
      for (int j = 0; j < 4; j++)
        acc[i][j] = fmaf(a[i], b4[j], acc[i][j]);
  }
  #pragma unroll
  for (int i = 0; i < 4; i++)
    #pragma unroll
    for (int j = 0; j < 4; j++)
      Cb[(size_t)(l0 + ty*4 + i) * LSEQ + s0 + tx*4 + j] = acc[i][j] * 0.125f;
}

// ---------------- softmax over rows of 1024, in place ----------------
__global__ void __launch_bounds__(256) softmax_kernel(float* __restrict__ p)
{
  __shared__ float sh[8];
  const size_t row = blockIdx.x;
  float4* rp = (float4*)(p + row * LSEQ);
  float4 v = rp[threadIdx.x];
  float m = fmaxf(fmaxf(v.x, v.y), fmaxf(v.z, v.w));
  #pragma unroll
  for (int o = 16; o > 0; o >>= 1) m = fmaxf(m, __shfl_xor_sync(0xffffffffu, m, o));
  if ((threadIdx.x & 31) == 0) sh[threadIdx.x >> 5] = m;
  __syncthreads();
  m = sh[0];
  #pragma unroll
  for (int i = 1; i < 8; i++) m = fmaxf(m, sh[i]);
  v.x = __expf(v.x - m); v.y = __expf(v.y - m);
  v.z = __expf(v.z - m); v.w = __expf(v.w - m);
  float s = v.x + v.y + v.z + v.w;
  #pragma unroll
  for (int o = 16; o > 0; o >>= 1) s += __shfl_xor_sync(0xffffffffu, s, o);
  __syncthreads();
  if ((threadIdx.x & 31) == 0) sh[threadIdx.x >> 5] = s;
  __syncthreads();
  s = sh[0]+sh[1]+sh[2]+sh[3]+sh[4]+sh[5]+sh[6]+sh[7];
  float inv = 1.f / s;
  v.x *= inv; v.y *= inv; v.z *= inv; v.w *= inv;
  rp[threadIdx.x] = v;
}

// ---------------- ctx[b,l,h,:] = sum_s attn[z,l,s] * V[b,s,h,:] ----------------
// grid (16 l-tiles, 64 bh); 64(L) x 64(hd) tile, k-loop over S in steps of 32.
__global__ void __launch_bounds__(256) attn_v_kernel(
    const float* __restrict__ attn, const float* __restrict__ V,
    float* __restrict__ ctx)
{
  const int z = blockIdx.y;
  const int b = z >> 3, h = z & 7;
  const int l0 = blockIdx.x * 64;
  const float* Ab = attn + (size_t)z * LSEQ * LSEQ;
  const float* Vb = V + (size_t)b * LSEQ * D + h * HD;
  float* Cb = ctx + (size_t)b * LSEQ * D + h * HD;
  __shared__ float As[32][65];   // [s][l]
  __shared__ float Vs[32][64];   // [s][c]
  const int tid = threadIdx.x;
  const int tx = tid & 15, ty = tid >> 4;
  float acc[4][4] = {};
  for (int s0 = 0; s0 < LSEQ; s0 += 32) {
    #pragma unroll
    for (int it = 0; it < 2; ++it) {
      int idx = tid + it * 256;     // 0..511
      int l   = idx >> 3;           // 0..63
      int s4  = (idx & 7) * 4;
      float4 va = *(const float4*)&Ab[(size_t)(l0 + l) * LSEQ + s0 + s4];
      As[s4+0][l] = va.x; As[s4+1][l] = va.y; As[s4+2][l] = va.z; As[s4+3][l] = va.w;
      int s   = idx >> 4;           // 0..31
      int c4  = (idx & 15) * 4;
      float4 vv = *(const float4*)&Vb[(size_t)(s0 + s) * D + c4];
      *(float4*)&Vs[s][c4] = vv;
    }
    __syncthreads();
    #pragma unroll
    for (int k = 0; k < 32; k++) {
      float a[4], b4[4];
      #pragma unroll
      for (int i = 0; i < 4; i++) a[i]  = As[k][ty*4 + i];
      #pragma unroll
      for (int j = 0; j < 4; j++) b4[j] = Vs[k][tx*4 + j];
      #pragma unroll
      for (int i = 0; i < 4; i++)
        #pragma unroll
        for (int j = 0; j < 4; j++)
          acc[i][j] = fmaf(a[i], b4[j], acc[i][j]);
    }
    __syncthreads();
  }
  #pragma unroll
  for (int i = 0; i < 4; i++) {
    int l = l0 + ty*4 + i;
    #pragma unroll
    for (int j = 0; j < 4; j++)
      Cb[(size_t)l * D + tx*4 + j] = acc[i][j];
  }
}

// ---------------- out = LN(x + y) * g + b, rows of 512 ----------------
__global__ void __launch_bounds__(256) residual_ln_kernel(
    const float* __restrict__ x, const float* __restrict__ y,
    const float* __restrict__ g, const float* __restrict__ b,
    float* __restrict__ out)
{
  __shared__ float shs[8], shq[8];
  const size_t row = blockIdx.x;
  const int t = threadIdx.x;
  float2 xa = ((const float2*)x)[row * 256 + t];
  float2 ya = ((const float2*)y)[row * 256 + t];
  float v0 = xa.x + ya.x, v1 = xa.y + ya.y;
  float s = v0 + v1, q = v0*v0 + v1*v1;
  #pragma unroll
  for (int o = 16; o > 0; o >>= 1) {
    s += __shfl_xor_sync(0xffffffffu, s, o);
    q += __shfl_xor_sync(0xffffffffu, q, o);
  }
  if ((t & 31) == 0) { shs[t >> 5] = s; shq[t >> 5] = q; }
  __syncthreads();
  s = 0.f; q = 0.f;
  #pragma unroll
  for (int i = 0; i < 8; i++) { s += shs[i]; q += shq[i]; }
  float mu  = s * (1.f / 512.f);
  float var = q * (1.f / 512.f) - mu * mu;
  float inv = rsqrtf(var + 1e-5f);
  float2 gg = ((const float2*)g)[t];
  float2 bb = ((const float2*)b)[t];
  float2 o2;
  o2.x = (v0 - mu) * inv * gg.x + bb.x;
  o2.y = (v1 - mu) * inv * gg.y + bb.y;
  ((float2*)out)[row * 256 + t] = o2;
}

// ---------------- host-side orchestration ----------------
static void launch_mha(const float* qin, const float* kvin,
                       const float* win, const float* bin,
                       const float* wout, const float* bout,
                       const float* g, const float* b,
                       const float* resid, float* attn, float* xout,
                       float* gq, float* gk, float* gv, float* gctx, float* gproj)
{
  gemm_tn<<<dim3(D/128, ROWS/128), 256>>>(qin,  win,          bin,        gq,   ROWS, D, D, 0);
  gemm_tn<<<dim3(D/128, ROWS/128), 256>>>(kvin, win +   D*D,  bin +   D,  gk,   ROWS, D, D, 0);
  gemm_tn<<<dim3(D/128, ROWS/128), 256>>>(kvin, win + 2*D*D,  bin + 2*D,  gv,   ROWS, D, D, 0);
  scores_kernel<<<dim3(16, 16, BH), 256>>>(gq, gk, attn);
  softmax_kernel<<<BH * LSEQ, 256>>>(attn);
  attn_v_kernel<<<dim3(16, BH), 256>>>(attn, gv, gctx);
  gemm_tn<<<dim3(D/128, ROWS/128), 256>>>(gctx, wout, bout, gproj, ROWS, D, D, 0);
  residual_ln_kernel<<<ROWS, 256>>>(resid, gproj, g, b, xout);
}

extern "C" void kernel_launch(void* const* d_in, const int* in_sizes, int n_in,
                              void* d_out, int out_size)
{
  const float* x1    = (const float*)d_in[0];
  const float* x2    = (const float*)d_in[1];
  const float* win1  = (const float*)d_in[2];
  const float* bin1  = (const float*)d_in[3];
  const float* wout1 = (const float*)d_in[4];
  const float* bout1 = (const float*)d_in[5];
  const float* win2  = (const float*)d_in[6];
  const float* bin2  = (const float*)d_in[7];
  const float* wout2 = (const float*)d_in[8];
  const float* bout2 = (const float*)d_in[9];
  const float* g1    = (const float*)d_in[10];
  const float* b1    = (const float*)d_in[11];
  const float* g2    = (const float*)d_in[12];
  const float* b2    = (const float*)d_in[13];
  const float* fw1   = (const float*)d_in[14];
  const float* fb1   = (const float*)d_in[15];
  const float* fw2   = (const float*)d_in[16];
  const float* fb2   = (const float*)d_in[17];
  const float* g3    = (const float*)d_in[18];
  const float* b3    = (const float*)d_in[19];

  float* out = (float*)d_out;
  float* ox1 = out;                                  // x1 final  (8,1024,512)
  float* ox2 = out + (size_t)ROWS * D;               // x2 final
  float* w12 = out + (size_t)2 * ROWS * D;           // w_1to2 (8,8,1024,1024)
  float* w21 = w12 + (size_t)BH * LSEQ * LSEQ;       // w_2to1

  float *gq, *gk, *gv, *gctx, *gproj, *ghid, *gffn;
  cudaGetSymbolAddress((void**)&gq,    g_q);
  cudaGetSymbolAddress((void**)&gk,    g_k);
  cudaGetSymbolAddress((void**)&gv,    g_v);
  cudaGetSymbolAddress((void**)&gctx,  g_ctx);
  cudaGetSymbolAddress((void**)&gproj, g_proj);
  cudaGetSymbolAddress((void**)&ghid,  g_hid);
  cudaGetSymbolAddress((void**)&gffn,  g_ffn);

  // mha1: q from x1, kv from x2 -> x1_a = LN(x1 + attn_out1)
  launch_mha(x1, x2, win1, bin1, wout1, bout1, g1, b1, x1, w12, ox1,
             gq, gk, gv, gctx, gproj);
  // mha2: q from x2, kv from x1_a -> x2_a = LN(x2 + attn_out2)
  launch_mha(x2, ox1, win2, bin2, wout2, bout2, g2, b2, x2, w21, ox2,
             gq, gk, gv, gctx, gproj);

  // FFN on both streams at once: [x1_a; x2_a] is contiguous (16384, 512)
  gemm_tn<<<dim3((2*D)/128, (2*ROWS)/128), 256>>>(out,  fw1, fb1, ghid, 2*ROWS, 2*D, D, 1);
  gemm_tn<<<dim3(D/128, (2*ROWS)/128), 256>>>(ghid, fw2, fb2, gffn, 2*ROWS, D, 2*D, 0);
  residual_ln_kernel<<<2*ROWS, 256>>>(out, gffn, g3, b3, out);   // in-place per row
}

// round 3
// speedup vs baseline: 3.3334x; 3.3334x over previous
#include <cuda_runtime.h>
#include <cuda_bf16.h>
#include <math.h>
#include <stddef.h>
#include <stdint.h>

#define D 512
#define LSEQ 1024
#define BATCH 8
#define NH 8
#define HD 64
#define ROWS (BATCH*LSEQ)   /* 8192 */
#define BH (BATCH*NH)       /* 64   */

// ---------------- scratch (no allocations allowed) ----------------
__device__ float g_q[ROWS*D];
__device__ float g_k[ROWS*D];
__device__ float g_v[ROWS*D];
__device__ float g_ctx[ROWS*D];
__device__ float g_proj[ROWS*D];
__device__ float g_hid[(size_t)2*ROWS*2*D];   // 16384 x 1024
__device__ float g_ffn[(size_t)2*ROWS*D];     // 16384 x 512

// ======================= helpers =======================
__device__ __forceinline__ uint32_t smem_u32(const void* p) {
  uint32_t a;
  asm("{ .reg .u64 t; cvta.to.shared.u64 t, %1; cvt.u32.u64 %0, t; }"
      : "=r"(a) : "l"(p));
  return a;
}

#define LDSM_X4(r0, r1, r2, r3, addr) \
  asm volatile("ldmatrix.sync.aligned.m8n8.x4.shared.b16 {%0,%1,%2,%3}, [%4];" \
               : "=r"(r0), "=r"(r1), "=r"(r2), "=r"(r3) : "r"(addr))
#define LDSM_X4_T(r0, r1, r2, r3, addr) \
  asm volatile("ldmatrix.sync.aligned.m8n8.x4.trans.shared.b16 {%0,%1,%2,%3}, [%4];" \
               : "=r"(r0), "=r"(r1), "=r"(r2), "=r"(r3) : "r"(addr))

#define MMA_BF16(c, a, b) \
  asm volatile( \
    "mma.sync.aligned.m16n8k16.row.col.f32.bf16.bf16.f32 " \
    "{%0,%1,%2,%3}, {%4,%5,%6,%7}, {%8,%9}, {%0,%1,%2,%3};" \
    : "+f"((c)[0]), "+f"((c)[1]), "+f"((c)[2]), "+f"((c)[3]) \
    : "r"((a)[0]), "r"((a)[1]), "r"((a)[2]), "r"((a)[3]), \
      "r"((b)[0]), "r"((b)[1]))

// ======================= mma.sync GEMM =======================
// C[M,N] = alpha * A[M,K] @ op(B)^T + bias (optional relu)
//   A row-major (lda).
//   BT=0: B[N,K] row-major (ldb = k-stride).   (B operand is col-major n-k)
//   BT=1: B stored [K,N] (ldb = n-row stride); logical B[n,k] = Bm[k*ldb+n].
// Batched via grid.z: z -> (zb=z>>3, zh=z&7) offsets.
// Tiles: 128 x NT x 32-slab.  8 warps as 4(M) x 2(N).
template <int NT, int BT>
__global__ void __launch_bounds__(256) gemm_mma(
    const float* __restrict__ A, const float* __restrict__ B,
    const float* __restrict__ bias, float* __restrict__ C,
    int nslab, int lda, int ldb, int ldc,
    long sAb, long sAh, long sBb, long sBh, long sCb, long sCh,
    float alpha, int relu)
{
  constexpr int NFRAG = NT / 16;           // n8 frags per warp
  constexpr int BROWS = BT ? 32 : NT;
  constexpr int BCOL  = BT ? NT + 8 : 40;  // padded row length (elems)

  __shared__ __align__(16) __nv_bfloat16 As[2][128][40];
  __shared__ __align__(16) __nv_bfloat16 Bs[2][BROWS][BCOL];

  const int tid = threadIdx.x;
  const int wid = tid >> 5, l = tid & 31;
  const int warp_m = wid & 3, warp_n = wid >> 2;
  const int nbase = warp_n * (NT / 2);

  const int z  = blockIdx.z;
  const int zb = z >> 3, zh = z & 7;
  A += (size_t)zb * sAb + (size_t)zh * sAh;
  B += (size_t)zb * sBb + (size_t)zh * sBh;
  C += (size_t)zb * sCb + (size_t)zh * sCh;
  const int bm = blockIdx.y * 128;
  const int bn = blockIdx.x * NT;

  float acc[2][NFRAG][4];
  #pragma unroll
  for (int i = 0; i < 2; i++)
    #pragma unroll
    for (int j = 0; j < NFRAG; j++)
      #pragma unroll
      for (int k = 0; k < 4; k++) acc[i][j][k] = 0.f;

  auto load_slab = [&](int slab, int buf) {
    const int k0 = slab << 5;
    // A: 128 rows x 32 k  -> 1024 float4
    #pragma unroll
    for (int it = 0; it < 4; ++it) {
      int idx = tid + it * 256;
      int r = idx >> 3, c4 = (idx & 7) << 2;
      float4 v = *(const float4*)(A + (size_t)(bm + r) * lda + k0 + c4);
      __nv_bfloat162 p0 = __floats2bfloat162_rn(v.x, v.y);
      __nv_bfloat162 p1 = __floats2bfloat162_rn(v.z, v.w);
      *(uint2*)&As[buf][r][c4] = make_uint2(*(uint32_t*)&p0, *(uint32_t*)&p1);
    }
    if (!BT) {
      #pragma unroll
      for (int it = 0; it < NT / 32; ++it) {
        int idx = tid + it * 256;
        int r = idx >> 3, c4 = (idx & 7) << 2;
        float4 v = *(const float4*)(B + (size_t)(bn + r) * ldb + k0 + c4);
        __nv_bfloat162 p0 = __floats2bfloat162_rn(v.x, v.y);
        __nv_bfloat162 p1 = __floats2bfloat162_rn(v.z, v.w);
        *(uint2*)&Bs[buf][r][c4] = make_uint2(*(uint32_t*)&p0, *(uint32_t*)&p1);
      }
    } else {
      // B stored [K,N]: 32 k-rows x NT n-cols
      #pragma unroll
      for (int it = 0; it < NT / 32; ++it) {
        int idx = tid + it * 256;
        int r  = idx / (NT / 4);
        int c4 = (idx % (NT / 4)) << 2;
        float4 v = *(const float4*)(B + (size_t)(k0 + r) * ldb + bn + c4);
        __nv_bfloat162 p0 = __floats2bfloat162_rn(v.x, v.y);
        __nv_bfloat162 p1 = __floats2bfloat162_rn(v.z, v.w);
        *(uint2*)&Bs[buf][r][c4] = make_uint2(*(uint32_t*)&p0, *(uint32_t*)&p1);
      }
    }
  };

  load_slab(0, 0);
  __syncthreads();

  int buf = 0;
  for (int i = 0; i < nslab; i++) {
    if (i + 1 < nslab) load_slab(i + 1, buf ^ 1);

    const uint32_t a_base = smem_u32(&As[buf][0][0]);
    const uint32_t b_base = smem_u32(&Bs[buf][0][0]);
    #pragma unroll
    for (int ks = 0; ks < 2; ks++) {
      const int k0 = ks * 16;
      uint32_t afr[2][4];
      #pragma unroll
      for (int mf = 0; mf < 2; mf++) {
        int row = warp_m * 32 + mf * 16 + (l & 15);
        uint32_t addr = a_base + (uint32_t)(row * 80 + (k0 + ((l >> 4) << 3)) * 2);
        LDSM_X4(afr[mf][0], afr[mf][1], afr[mf][2], afr[mf][3], addr);
      }
      uint32_t bfr[NFRAG][2];
      #pragma unroll
      for (int nf = 0; nf < NFRAG; nf += 2) {
        uint32_t addr;
        if (!BT) {
          int row = nbase + nf * 8 + ((l >> 4) << 3) + (l & 7);
          int col = k0 + ((l >> 3) & 1) * 8;
          addr = b_base + (uint32_t)(row * 80 + col * 2);
          LDSM_X4(bfr[nf][0], bfr[nf][1], bfr[nf + 1][0], bfr[nf + 1][1], addr);
        } else {
          int krow = k0 + ((l >> 3) & 1) * 8 + (l & 7);
          int ncol = nbase + nf * 8 + ((l >> 4) << 3);
          addr = b_base + (uint32_t)(krow * (BCOL * 2) + ncol * 2);
          LDSM_X4_T(bfr[nf][0], bfr[nf][1], bfr[nf + 1][0], bfr[nf + 1][1], addr);
        }
      }
      #pragma unroll
      for (int mf = 0; mf < 2; mf++)
        #pragma unroll
        for (int nf = 0; nf < NFRAG; nf++)
          MMA_BF16(acc[mf][nf], afr[mf], bfr[nf]);
    }
    __syncthreads();
    buf ^= 1;
  }

  // ---------------- epilogue ----------------
  const int gid = l >> 2, tig = l & 3;
  #pragma unroll
  for (int mf = 0; mf < 2; mf++) {
    const int row = bm + warp_m * 32 + mf * 16 + gid;
    #pragma unroll
    for (int nf = 0; nf < NFRAG; nf++) {
      const int col = bn + nbase + nf * 8 + tig * 2;
      float2 bv = make_float2(0.f, 0.f);
      if (bias) bv = *(const float2*)(bias + col);
      float2 v0, v1;
      v0.x = fmaf(alpha, acc[mf][nf][0], bv.x);
      v0.y = fmaf(alpha, acc[mf][nf][1], bv.y);
      v1.x = fmaf(alpha, acc[mf][nf][2], bv.x);
      v1.y = fmaf(alpha, acc[mf][nf][3], bv.y);
      if (relu) {
        v0.x = fmaxf(v0.x, 0.f); v0.y = fmaxf(v0.y, 0.f);
        v1.x = fmaxf(v1.x, 0.f); v1.y = fmaxf(v1.y, 0.f);
      }
      *(float2*)(C + (size_t)row * ldc + col) = v0;
      *(float2*)(C + (size_t)(row + 8) * ldc + col) = v1;
    }
  }
}

// ---------------- softmax over rows of 1024, in place ----------------
__global__ void __launch_bounds__(256) softmax_kernel(float* __restrict__ p)
{
  __shared__ float sh[8];
  const size_t row = blockIdx.x;
  float4* rp = (float4*)(p + row * LSEQ);
  float4 v = rp[threadIdx.x];
  float m = fmaxf(fmaxf(v.x, v.y), fmaxf(v.z, v.w));
  #pragma unroll
  for (int o = 16; o > 0; o >>= 1) m = fmaxf(m, __shfl_xor_sync(0xffffffffu, m, o));
  if ((threadIdx.x & 31) == 0) sh[threadIdx.x >> 5] = m;
  __syncthreads();
  m = sh[0];
  #pragma unroll
  for (int i = 1; i < 8; i++) m = fmaxf(m, sh[i]);
  v.x = __expf(v.x - m); v.y = __expf(v.y - m);
  v.z = __expf(v.z - m); v.w = __expf(v.w - m);
  float s = v.x + v.y + v.z + v.w;
  #pragma unroll
  for (int o = 16; o > 0; o >>= 1) s += __shfl_xor_sync(0xffffffffu, s, o);
  __syncthreads();
  if ((threadIdx.x & 31) == 0) sh[threadIdx.x >> 5] = s;
  __syncthreads();
  s = sh[0]+sh[1]+sh[2]+sh[3]+sh[4]+sh[5]+sh[6]+sh[7];
  float inv = 1.f / s;
  v.x *= inv; v.y *= inv; v.z *= inv; v.w *= inv;
  rp[threadIdx.x] = v;
}

// ---------------- out = LN(x + y) * g + b, rows of 512 ----------------
__global__ void __launch_bounds__(256) residual_ln_kernel(
    const float* __restrict__ x, const float* __restrict__ y,
    const float* __restrict__ g, const float* __restrict__ b,
    float* __restrict__ out)
{
  __shared__ float shs[8], shq[8];
  const size_t row = blockIdx.x;
  const int t = threadIdx.x;
  float2 xa = ((const float2*)x)[row * 256 + t];
  float2 ya = ((const float2*)y)[row * 256 + t];
  float v0 = xa.x + ya.x, v1 = xa.y + ya.y;
  float s = v0 + v1, q = v0*v0 + v1*v1;
  #pragma unroll
  for (int o = 16; o > 0; o >>= 1) {
    s += __shfl_xor_sync(0xffffffffu, s, o);
    q += __shfl_xor_sync(0xffffffffu, q, o);
  }
  if ((t & 31) == 0) { shs[t >> 5] = s; shq[t >> 5] = q; }
  __syncthreads();
  s = 0.f; q = 0.f;
  #pragma unroll
  for (int i = 0; i < 8; i++) { s += shs[i]; q += shq[i]; }
  float mu  = s * (1.f / 512.f);
  float var = q * (1.f / 512.f) - mu * mu;
  float inv = rsqrtf(var + 1e-5f);
  float2 gg = ((const float2*)g)[t];
  float2 bb = ((const float2*)b)[t];
  float2 o2;
  o2.x = (v0 - mu) * inv * gg.x + bb.x;
  o2.y = (v1 - mu) * inv * gg.y + bb.y;
  ((float2*)out)[row * 256 + t] = o2;
}

// ---------------- host-side orchestration ----------------
static void dense_gemm(const float* A, const float* B, const float* bias, float* C,
                       int M, int N, int K, int relu)
{
  gemm_mma<128, 0><<<dim3(N / 128, M / 128, 1), 256>>>(
      A, B, bias, C, K / 32, K, K, N,
      0, 0, 0, 0, 0, 0, 1.f, relu);
}

static void launch_mha(const float* qin, const float* kvin,
                       const float* win, const float* bin,
                       const float* wout, const float* bout,
                       const float* g, const float* b,
                       const float* resid, float* attn, float* xout,
                       float* gq, float* gk, float* gv, float* gctx, float* gproj)
{
  dense_gemm(qin,  win,          bin,        gq, ROWS, D, D, 0);
  dense_gemm(kvin, win +   D*D,  bin +   D,  gk, ROWS, D, D, 0);
  dense_gemm(kvin, win + 2*D*D,  bin + 2*D,  gv, ROWS, D, D, 0);

  // scores: per (b,h): [1024,1024] = Q[b,:,h,:] @ K[b,:,h,:]^T / 8
  gemm_mma<128, 0><<<dim3(8, 8, BH), 256>>>(
      gq, gk, nullptr, attn, HD / 32, D, D, LSEQ,
      (long)LSEQ * D, HD, (long)LSEQ * D, HD,
      (long)NH * LSEQ * LSEQ, (long)LSEQ * LSEQ, 0.125f, 0);

  softmax_kernel<<<BH * LSEQ, 256>>>(attn);

  // ctx: per (b,h): [1024,64] = attn @ V[b,:,h,:]   (B stored [K=s, N=c])
  gemm_mma<64, 1><<<dim3(1, 8, BH), 256>>>(
      attn, gv, nullptr, gctx, LSEQ / 32, LSEQ, D, D,
      (long)NH * LSEQ * LSEQ, (long)LSEQ * LSEQ, (long)LSEQ * D, HD,
      (long)LSEQ * D, HD, 1.f, 0);

  dense_gemm(gctx, wout, bout, gproj, ROWS, D, D, 0);
  residual_ln_kernel<<<ROWS, 256>>>(resid, gproj, g, b, xout);
}

extern "C" void kernel_launch(void* const* d_in, const int* in_sizes, int n_in,
                              void* d_out, int out_size)
{
  const float* x1    = (const float*)d_in[0];
  const float* x2    = (const float*)d_in[1];
  const float* win1  = (const float*)d_in[2];
  const float* bin1  = (const float*)d_in[3];
  const float* wout1 = (const float*)d_in[4];
  const float* bout1 = (const float*)d_in[5];
  const float* win2  = (const float*)d_in[6];
  const float* bin2  = (const float*)d_in[7];
  const float* wout2 = (const float*)d_in[8];
  const float* bout2 = (const float*)d_in[9];
  const float* g1    = (const float*)d_in[10];
  const float* b1    = (const float*)d_in[11];
  const float* g2    = (const float*)d_in[12];
  const float* b2    = (const float*)d_in[13];
  const float* fw1   = (const float*)d_in[14];
  const float* fb1   = (const float*)d_in[15];
  const float* fw2   = (const float*)d_in[16];
  const float* fb2   = (const float*)d_in[17];
  const float* g3    = (const float*)d_in[18];
  const float* b3    = (const float*)d_in[19];

  float* out = (float*)d_out;
  float* ox1 = out;
  float* ox2 = out + (size_t)ROWS * D;
  float* w12 = out + (size_t)2 * ROWS * D;
  float* w21 = w12 + (size_t)BH * LSEQ * LSEQ;

  float *gq, *gk, *gv, *gctx, *gproj, *ghid, *gffn;
  cudaGetSymbolAddress((void**)&gq,    g_q);
  cudaGetSymbolAddress((void**)&gk,    g_k);
  cudaGetSymbolAddress((void**)&gv,    g_v);
  cudaGetSymbolAddress((void**)&gctx,  g_ctx);
  cudaGetSymbolAddress((void**)&gproj, g_proj);
  cudaGetSymbolAddress((void**)&ghid,  g_hid);
  cudaGetSymbolAddress((void**)&gffn,  g_ffn);

  // mha1: q from x1, kv from x2 -> x1_a = LN(x1 + attn_out1)
  launch_mha(x1, x2, win1, bin1, wout1, bout1, g1, b1, x1, w12, ox1,
             gq, gk, gv, gctx, gproj);
  // mha2: q from x2, kv from x1_a -> x2_a = LN(x2 + attn_out2)
  launch_mha(x2, ox1, win2, bin2, wout2, bout2, g2, b2, x2, w21, ox2,
             gq, gk, gv, gctx, gproj);

  // FFN on both streams at once: [x1_a; x2_a] contiguous (16384, 512)
  dense_gemm(out,  fw1, fb1, ghid, 2*ROWS, 2*D, D, 1);
  dense_gemm(ghid, fw2, fb2, gffn, 2*ROWS, D, 2*D, 0);
  residual_ln_kernel<<<2*ROWS, 256>>>(out, gffn, g3, b3, out);
}

// round 4
// speedup vs baseline: 4.1042x; 1.2312x over previous
#include <cuda_runtime.h>
#include <cuda_bf16.h>
#include <math.h>
#include <stddef.h>
#include <stdint.h>

#define D 512
#define LSEQ 1024
#define BATCH 8
#define NH 8
#define HD 64
#define ROWS (BATCH*LSEQ)   /* 8192 */
#define BH (BATCH*NH)       /* 64   */

// ---------------- scratch (no allocations allowed) ----------------
__device__ float g_q[ROWS*D];
__device__ float g_kv[(size_t)ROWS*2*D];      // K cols 0..511, V cols 512..1023
__device__ float g_ctx[ROWS*D];
__device__ float g_proj[ROWS*D];
__device__ float g_hid[(size_t)2*ROWS*2*D];   // 16384 x 1024
__device__ float g_ffn[(size_t)2*ROWS*D];     // 16384 x 512

// ======================= helpers =======================
__device__ __forceinline__ uint32_t smem_u32(const void* p) {
  uint32_t a;
  asm("{ .reg .u64 t; cvta.to.shared.u64 t, %1; cvt.u32.u64 %0, t; }"
      : "=r"(a) : "l"(p));
  return a;
}

#define LDSM_X4(r0, r1, r2, r3, addr) \
  asm volatile("ldmatrix.sync.aligned.m8n8.x4.shared.b16 {%0,%1,%2,%3}, [%4];" \
               : "=r"(r0), "=r"(r1), "=r"(r2), "=r"(r3) : "r"(addr))
#define LDSM_X4_T(r0, r1, r2, r3, addr) \
  asm volatile("ldmatrix.sync.aligned.m8n8.x4.trans.shared.b16 {%0,%1,%2,%3}, [%4];" \
               : "=r"(r0), "=r"(r1), "=r"(r2), "=r"(r3) : "r"(addr))

#define MMA_BF16(c, a, b) \
  asm volatile( \
    "mma.sync.aligned.m16n8k16.row.col.f32.bf16.bf16.f32 " \
    "{%0,%1,%2,%3}, {%4,%5,%6,%7}, {%8,%9}, {%0,%1,%2,%3};" \
    : "+f"((c)[0]), "+f"((c)[1]), "+f"((c)[2]), "+f"((c)[3]) \
    : "r"((a)[0]), "r"((a)[1]), "r"((a)[2]), "r"((a)[3]), \
      "r"((b)[0]), "r"((b)[1]))

// ======================= mma.sync GEMM (dense projections / FFN) ==========
// C[M,N] = alpha * A[M,K] @ B^T + bias (optional relu); B[N,K] row-major.
template <int NT>
__global__ void __launch_bounds__(256) gemm_mma(
    const float* __restrict__ A, const float* __restrict__ B,
    const float* __restrict__ bias, float* __restrict__ C,
    int nslab, int lda, int ldb, int ldc, float alpha, int relu)
{
  constexpr int NFRAG = NT / 16;

  __shared__ __align__(16) __nv_bfloat16 As[2][128][40];
  __shared__ __align__(16) __nv_bfloat16 Bs[2][NT][40];

  const int tid = threadIdx.x;
  const int wid = tid >> 5, l = tid & 31;
  const int warp_m = wid & 3, warp_n = wid >> 2;
  const int nbase = warp_n * (NT / 2);

  const int bm = blockIdx.y * 128;
  const int bn = blockIdx.x * NT;

  float acc[2][NFRAG][4];
  #pragma unroll
  for (int i = 0; i < 2; i++)
    #pragma unroll
    for (int j = 0; j < NFRAG; j++)
      #pragma unroll
      for (int k = 0; k < 4; k++) acc[i][j][k] = 0.f;

  auto load_slab = [&](int slab, int buf) {
    const int k0 = slab << 5;
    #pragma unroll
    for (int it = 0; it < 4; ++it) {
      int idx = tid + it * 256;
      int r = idx >> 3, c4 = (idx & 7) << 2;
      float4 v = *(const float4*)(A + (size_t)(bm + r) * lda + k0 + c4);
      __nv_bfloat162 p0 = __floats2bfloat162_rn(v.x, v.y);
      __nv_bfloat162 p1 = __floats2bfloat162_rn(v.z, v.w);
      *(uint2*)&As[buf][r][c4] = make_uint2(*(uint32_t*)&p0, *(uint32_t*)&p1);
    }
    #pragma unroll
    for (int it = 0; it < NT / 32; ++it) {
      int idx = tid + it * 256;
      int r = idx >> 3, c4 = (idx & 7) << 2;
      float4 v = *(const float4*)(B + (size_t)(bn + r) * ldb + k0 + c4);
      __nv_bfloat162 p0 = __floats2bfloat162_rn(v.x, v.y);
      __nv_bfloat162 p1 = __floats2bfloat162_rn(v.z, v.w);
      *(uint2*)&Bs[buf][r][c4] = make_uint2(*(uint32_t*)&p0, *(uint32_t*)&p1);
    }
  };

  load_slab(0, 0);
  __syncthreads();

  int buf = 0;
  for (int i = 0; i < nslab; i++) {
    if (i + 1 < nslab) load_slab(i + 1, buf ^ 1);

    const uint32_t a_base = smem_u32(&As[buf][0][0]);
    const uint32_t b_base = smem_u32(&Bs[buf][0][0]);
    #pragma unroll
    for (int ks = 0; ks < 2; ks++) {
      const int k0 = ks * 16;
      uint32_t afr[2][4];
      #pragma unroll
      for (int mf = 0; mf < 2; mf++) {
        int row = warp_m * 32 + mf * 16 + (l & 15);
        uint32_t addr = a_base + (uint32_t)(row * 80 + (k0 + ((l >> 4) << 3)) * 2);
        LDSM_X4(afr[mf][0], afr[mf][1], afr[mf][2], afr[mf][3], addr);
      }
      uint32_t bfr[NFRAG][2];
      #pragma unroll
      for (int nf = 0; nf < NFRAG; nf += 2) {
        int row = nbase + nf * 8 + ((l >> 4) << 3) + (l & 7);
        int col = k0 + ((l >> 3) & 1) * 8;
        uint32_t addr = b_base + (uint32_t)(row * 80 + col * 2);
        LDSM_X4(bfr[nf][0], bfr[nf][1], bfr[nf + 1][0], bfr[nf + 1][1], addr);
      }
      #pragma unroll
      for (int mf = 0; mf < 2; mf++)
        #pragma unroll
        for (int nf = 0; nf < NFRAG; nf++)
          MMA_BF16(acc[mf][nf], afr[mf], bfr[nf]);
    }
    __syncthreads();
    buf ^= 1;
  }

  const int gid = l >> 2, tig = l & 3;
  #pragma unroll
  for (int mf = 0; mf < 2; mf++) {
    const int row = bm + warp_m * 32 + mf * 16 + gid;
    #pragma unroll
    for (int nf = 0; nf < NFRAG; nf++) {
      const int col = bn + nbase + nf * 8 + tig * 2;
      float2 bv = make_float2(0.f, 0.f);
      if (bias) bv = *(const float2*)(bias + col);
      float2 v0, v1;
      v0.x = fmaf(alpha, acc[mf][nf][0], bv.x);
      v0.y = fmaf(alpha, acc[mf][nf][1], bv.y);
      v1.x = fmaf(alpha, acc[mf][nf][2], bv.x);
      v1.y = fmaf(alpha, acc[mf][nf][3], bv.y);
      if (relu) {
        v0.x = fmaxf(v0.x, 0.f); v0.y = fmaxf(v0.y, 0.f);
        v1.x = fmaxf(v1.x, 0.f); v1.y = fmaxf(v1.y, 0.f);
      }
      *(float2*)(C + (size_t)row * ldc + col) = v0;
      *(float2*)(C + (size_t)(row + 8) * ldc + col) = v1;
    }
  }
}

// ======================= fused attention ============================
// Per block: bh = blockIdx.y, 128 q-rows at l0 = blockIdx.x*128.
// Pass 1: Z[row] = sum_s exp(S[row,s]),  S = QK^T/8 (bf16 MMA, fp32 acc).
// Pass 2: recompute S, P = exp(S)/Z -> gmem (fp32), P(bf16)@V -> ctx.
// SMEM offsets (bytes):
#define FA_QS   0
#define FA_KS   18432
#define FA_VS   36864
#define FA_PS   55296
#define FA_ZS   90112
#define FA_SMEM 90624

__global__ void __launch_bounds__(256) fused_attn(
    const float* __restrict__ Q, const float* __restrict__ KV,
    float* __restrict__ attn, float* __restrict__ ctx)
{
  extern __shared__ char sm[];
  __nv_bfloat16* Qs = (__nv_bfloat16*)(sm + FA_QS);   // [128][72]
  __nv_bfloat16* Ks = (__nv_bfloat16*)(sm + FA_KS);   // [128][72]
  __nv_bfloat16* Vs = (__nv_bfloat16*)(sm + FA_VS);   // [128][72]
  __nv_bfloat16* Ps = (__nv_bfloat16*)(sm + FA_PS);   // [128][136]
  float*         Zs = (float*)(sm + FA_ZS);           // [128]

  const int tid = threadIdx.x;
  const int wid = tid >> 5, l = tid & 31;
  const int warp_m = wid & 3, warp_n = wid >> 2;
  const int gid = l >> 2, tig = l & 3;

  const int z = blockIdx.y;
  const int b = z >> 3, h = z & 7;
  const int l0 = blockIdx.x * 128;

  const float* Qg = Q  + (size_t)b * LSEQ * D + h * HD;        // row stride D
  const float* Kg = KV + (size_t)b * LSEQ * 2 * D + h * HD;    // row stride 2D
  const float* Vg = Kg + D;
  float* Pg = attn + (size_t)z * LSEQ * LSEQ;
  float* Og = ctx + (size_t)b * LSEQ * D + h * HD;

  // ---- init: load Q tile (128x64), zero Zs ----
  if (tid < 128) Zs[tid] = 0.f;
  #pragma unroll
  for (int it = 0; it < 8; ++it) {         // 128*16 float4
    int idx = tid + it * 256;
    int r = idx >> 4, c4 = (idx & 15) << 2;
    float4 v = *(const float4*)(Qg + (size_t)(l0 + r) * D + c4);
    __nv_bfloat162 p0 = __floats2bfloat162_rn(v.x, v.y);
    __nv_bfloat162 p1 = __floats2bfloat162_rn(v.z, v.w);
    *(uint2*)&Qs[r * 72 + c4] = make_uint2(*(uint32_t*)&p0, *(uint32_t*)&p1);
  }
  __syncthreads();

  const uint32_t qsb = smem_u32(Qs);
  const uint32_t ksb = smem_u32(Ks);
  const uint32_t vsb = smem_u32(Vs);
  const uint32_t psb = smem_u32(Ps);

  auto load_k = [&](int s0) {
    #pragma unroll
    for (int it = 0; it < 8; ++it) {
      int idx = tid + it * 256;
      int r = idx >> 4, c4 = (idx & 15) << 2;
      float4 v = *(const float4*)(Kg + (size_t)(s0 + r) * 2 * D + c4);
      __nv_bfloat162 p0 = __floats2bfloat162_rn(v.x, v.y);
      __nv_bfloat162 p1 = __floats2bfloat162_rn(v.z, v.w);
      *(uint2*)&Ks[r * 72 + c4] = make_uint2(*(uint32_t*)&p0, *(uint32_t*)&p1);
    }
  };
  auto load_v = [&](int s0) {
    #pragma unroll
    for (int it = 0; it < 8; ++it) {
      int idx = tid + it * 256;
      int r = idx >> 4, c4 = (idx & 15) << 2;
      float4 v = *(const float4*)(Vg + (size_t)(s0 + r) * 2 * D + c4);
      __nv_bfloat162 p0 = __floats2bfloat162_rn(v.x, v.y);
      __nv_bfloat162 p1 = __floats2bfloat162_rn(v.z, v.w);
      *(uint2*)&Vs[r * 72 + c4] = make_uint2(*(uint32_t*)&p0, *(uint32_t*)&p1);
    }
  };

  // S-frag compute into acc[2][8][4] (S = QK^T, no scale yet)
  auto s_mma = [&](float (*acc)[8][4]) {
    #pragma unroll
    for (int i = 0; i < 2; i++)
      #pragma unroll
      for (int j = 0; j < 8; j++)
        #pragma unroll
        for (int k = 0; k < 4; k++) acc[i][j][k] = 0.f;
    #pragma unroll
    for (int ks = 0; ks < 4; ks++) {
      const int k0 = ks * 16;
      uint32_t afr[2][4];
      #pragma unroll
      for (int mf = 0; mf < 2; mf++) {
        int row = warp_m * 32 + mf * 16 + (l & 15);
        uint32_t addr = qsb + (uint32_t)(row * 144 + (k0 + ((l >> 4) << 3)) * 2);
        LDSM_X4(afr[mf][0], afr[mf][1], afr[mf][2], afr[mf][3], addr);
      }
      uint32_t bfr[8][2];
      #pragma unroll
      for (int nf = 0; nf < 8; nf += 2) {
        int row = warp_n * 64 + nf * 8 + ((l >> 4) << 3) + (l & 7);
        int col = k0 + ((l >> 3) & 1) * 8;
        uint32_t addr = ksb + (uint32_t)(row * 144 + col * 2);
        LDSM_X4(bfr[nf][0], bfr[nf][1], bfr[nf + 1][0], bfr[nf + 1][1], addr);
      }
      #pragma unroll
      for (int mf = 0; mf < 2; mf++)
        #pragma unroll
        for (int nf = 0; nf < 8; nf++)
          MMA_BF16(acc[mf][nf], afr[mf], bfr[nf]);
    }
  };

  // ================= pass 1: row sums =================
  {
    float zr[2][2] = {{0.f, 0.f}, {0.f, 0.f}};
    for (int st = 0; st < 8; st++) {
      load_k(st * 128);
      __syncthreads();
      float acc[2][8][4];
      s_mma(acc);
      #pragma unroll
      for (int mf = 0; mf < 2; mf++)
        #pragma unroll
        for (int nf = 0; nf < 8; nf++) {
          zr[mf][0] += __expf(acc[mf][nf][0] * 0.125f) + __expf(acc[mf][nf][1] * 0.125f);
          zr[mf][1] += __expf(acc[mf][nf][2] * 0.125f) + __expf(acc[mf][nf][3] * 0.125f);
        }
      __syncthreads();
    }
    #pragma unroll
    for (int mf = 0; mf < 2; mf++)
      #pragma unroll
      for (int rp = 0; rp < 2; rp++) {
        float v = zr[mf][rp];
        v += __shfl_xor_sync(0xffffffffu, v, 1);
        v += __shfl_xor_sync(0xffffffffu, v, 2);
        if (tig == 0)
          atomicAdd(&Zs[warp_m * 32 + mf * 16 + rp * 8 + gid], v);
      }
    __syncthreads();
    if (tid < 128) Zs[tid] = 1.f / Zs[tid];
    __syncthreads();
  }

  float iz[2][2];
  #pragma unroll
  for (int mf = 0; mf < 2; mf++)
    #pragma unroll
    for (int rp = 0; rp < 2; rp++)
      iz[mf][rp] = Zs[warp_m * 32 + mf * 16 + rp * 8 + gid];

  // ================= pass 2: write P, accumulate O = P@V =================
  float oacc[2][4][4];
  #pragma unroll
  for (int i = 0; i < 2; i++)
    #pragma unroll
    for (int j = 0; j < 4; j++)
      #pragma unroll
      for (int k = 0; k < 4; k++) oacc[i][j][k] = 0.f;

  for (int st = 0; st < 8; st++) {
    const int s0 = st * 128;
    load_k(s0);
    load_v(s0);
    __syncthreads();
    float acc[2][8][4];
    s_mma(acc);

    // P = exp(S/8) * invZ : write fp32 to gmem, bf16 to Ps
    #pragma unroll
    for (int mf = 0; mf < 2; mf++) {
      const int r0 = warp_m * 32 + mf * 16 + gid;
      #pragma unroll
      for (int nf = 0; nf < 8; nf++) {
        const int c = warp_n * 64 + nf * 8 + tig * 2;
        float p00 = __expf(acc[mf][nf][0] * 0.125f) * iz[mf][0];
        float p01 = __expf(acc[mf][nf][1] * 0.125f) * iz[mf][0];
        float p10 = __expf(acc[mf][nf][2] * 0.125f) * iz[mf][1];
        float p11 = __expf(acc[mf][nf][3] * 0.125f) * iz[mf][1];
        *(float2*)(Pg + (size_t)(l0 + r0) * LSEQ + s0 + c) = make_float2(p00, p01);
        *(float2*)(Pg + (size_t)(l0 + r0 + 8) * LSEQ + s0 + c) = make_float2(p10, p11);
        __nv_bfloat162 q0 = __floats2bfloat162_rn(p00, p01);
        __nv_bfloat162 q1 = __floats2bfloat162_rn(p10, p11);
        *(uint32_t*)&Ps[r0 * 136 + c] = *(uint32_t*)&q0;
        *(uint32_t*)&Ps[(r0 + 8) * 136 + c] = *(uint32_t*)&q1;
      }
    }
    __syncthreads();

    // O += P @ V : A = Ps (128x128), B = Vs^T (col-major n over 64)
    #pragma unroll
    for (int ks = 0; ks < 8; ks++) {
      const int k0 = ks * 16;
      uint32_t afr[2][4];
      #pragma unroll
      for (int mf = 0; mf < 2; mf++) {
        int row = warp_m * 32 + mf * 16 + (l & 15);
        uint32_t addr = psb + (uint32_t)(row * 272 + (k0 + ((l >> 4) << 3)) * 2);
        LDSM_X4(afr[mf][0], afr[mf][1], afr[mf][2], afr[mf][3], addr);
      }
      uint32_t bfr[4][2];
      #pragma unroll
      for (int nf = 0; nf < 4; nf += 2) {
        int krow = k0 + ((l >> 3) & 1) * 8 + (l & 7);
        int ncol = warp_n * 32 + nf * 8 + ((l >> 4) << 3);
        uint32_t addr = vsb + (uint32_t)(krow * 144 + ncol * 2);
        LDSM_X4_T(bfr[nf][0], bfr[nf][1], bfr[nf + 1][0], bfr[nf + 1][1], addr);
      }
      #pragma unroll
      for (int mf = 0; mf < 2; mf++)
        #pragma unroll
        for (int nf = 0; nf < 4; nf++)
          MMA_BF16(oacc[mf][nf], afr[mf], bfr[nf]);
    }
    __syncthreads();
  }

  // ---- write ctx ----
  #pragma unroll
  for (int mf = 0; mf < 2; mf++) {
    const int r0 = l0 + warp_m * 32 + mf * 16 + gid;
    #pragma unroll
    for (int nf = 0; nf < 4; nf++) {
      const int c = warp_n * 32 + nf * 8 + tig * 2;
      *(float2*)(Og + (size_t)r0 * D + c) = make_float2(oacc[mf][nf][0], oacc[mf][nf][1]);
      *(float2*)(Og + (size_t)(r0 + 8) * D + c) = make_float2(oacc[mf][nf][2], oacc[mf][nf][3]);
    }
  }
}

// ---------------- out = LN(x + y) * g + b, rows of 512 ----------------
__global__ void __launch_bounds__(256) residual_ln_kernel(
    const float* __restrict__ x, const float* __restrict__ y,
    const float* __restrict__ g, const float* __restrict__ b,
    float* __restrict__ out)
{
  __shared__ float shs[8], shq[8];
  const size_t row = blockIdx.x;
  const int t = threadIdx.x;
  float2 xa = ((const float2*)x)[row * 256 + t];
  float2 ya = ((const float2*)y)[row * 256 + t];
  float v0 = xa.x + ya.x, v1 = xa.y + ya.y;
  float s = v0 + v1, q = v0*v0 + v1*v1;
  #pragma unroll
  for (int o = 16; o > 0; o >>= 1) {
    s += __shfl_xor_sync(0xffffffffu, s, o);
    q += __shfl_xor_sync(0xffffffffu, q, o);
  }
  if ((t & 31) == 0) { shs[t >> 5] = s; shq[t >> 5] = q; }
  __syncthreads();
  s = 0.f; q = 0.f;
  #pragma unroll
  for (int i = 0; i < 8; i++) { s += shs[i]; q += shq[i]; }
  float mu  = s * (1.f / 512.f);
  float var = q * (1.f / 512.f) - mu * mu;
  float inv = rsqrtf(var + 1e-5f);
  float2 gg = ((const float2*)g)[t];
  float2 bb = ((const float2*)b)[t];
  float2 o2;
  o2.x = (v0 - mu) * inv * gg.x + bb.x;
  o2.y = (v1 - mu) * inv * gg.y + bb.y;
  ((float2*)out)[row * 256 + t] = o2;
}

// ---------------- host-side orchestration ----------------
static void dense_gemm(const float* A, const float* B, const float* bias, float* C,
                       int M, int N, int K, int relu)
{
  gemm_mma<128><<<dim3(N / 128, M / 128, 1), 256>>>(
      A, B, bias, C, K / 32, K, K, N, 1.f, relu);
}

static void launch_mha(const float* qin, const float* kvin,
                       const float* win, const float* bin,
                       const float* wout, const float* bout,
                       const float* g, const float* b,
                       const float* resid, float* attn, float* xout,
                       float* gq, float* gkv, float* gctx, float* gproj)
{
  dense_gemm(qin,  win,         bin,       gq,  ROWS, D, D, 0);
  dense_gemm(kvin, win + D*D,   bin + D,   gkv, ROWS, 2*D, D, 0);   // K|V fused
  fused_attn<<<dim3(8, BH), 256, FA_SMEM>>>(gq, gkv, attn, gctx);
  dense_gemm(gctx, wout, bout, gproj, ROWS, D, D, 0);
  residual_ln_kernel<<<ROWS, 256>>>(resid, gproj, g, b, xout);
}

extern "C" void kernel_launch(void* const* d_in, const int* in_sizes, int n_in,
                              void* d_out, int out_size)
{
  const float* x1    = (const float*)d_in[0];
  const float* x2    = (const float*)d_in[1];
  const float* win1  = (const float*)d_in[2];
  const float* bin1  = (const float*)d_in[3];
  const float* wout1 = (const float*)d_in[4];
  const float* bout1 = (const float*)d_in[5];
  const float* win2  = (const float*)d_in[6];
  const float* bin2  = (const float*)d_in[7];
  const float* wout2 = (const float*)d_in[8];
  const float* bout2 = (const float*)d_in[9];
  const float* g1    = (const float*)d_in[10];
  const float* b1    = (const float*)d_in[11];
  const float* g2    = (const float*)d_in[12];
  const float* b2    = (const float*)d_in[13];
  const float* fw1   = (const float*)d_in[14];
  const float* fb1   = (const float*)d_in[15];
  const float* fw2   = (const float*)d_in[16];
  const float* fb2   = (const float*)d_in[17];
  const float* g3    = (const float*)d_in[18];
  const float* b3    = (const float*)d_in[19];

  cudaFuncSetAttribute(fused_attn, cudaFuncAttributeMaxDynamicSharedMemorySize, FA_SMEM);

  float* out = (float*)d_out;
  float* ox1 = out;
  float* ox2 = out + (size_t)ROWS * D;
  float* w12 = out + (size_t)2 * ROWS * D;
  float* w21 = w12 + (size_t)BH * LSEQ * LSEQ;

  float *gq, *gkv, *gctx, *gproj, *ghid, *gffn;
  cudaGetSymbolAddress((void**)&gq,    g_q);
  cudaGetSymbolAddress((void**)&gkv,   g_kv);
  cudaGetSymbolAddress((void**)&gctx,  g_ctx);
  cudaGetSymbolAddress((void**)&gproj, g_proj);
  cudaGetSymbolAddress((void**)&ghid,  g_hid);
  cudaGetSymbolAddress((void**)&gffn,  g_ffn);

  // mha1: q from x1, kv from x2 -> x1_a = LN(x1 + attn_out1)
  launch_mha(x1, x2, win1, bin1, wout1, bout1, g1, b1, x1, w12, ox1,
             gq, gkv, gctx, gproj);
  // mha2: q from x2, kv from x1_a -> x2_a = LN(x2 + attn_out2)
  launch_mha(x2, ox1, win2, bin2, wout2, bout2, g2, b2, x2, w21, ox2,
             gq, gkv, gctx, gproj);

  // FFN on both streams at once: [x1_a; x2_a] contiguous (16384, 512)
  dense_gemm(out,  fw1, fb1, ghid, 2*ROWS, 2*D, D, 1);
  dense_gemm(ghid, fw2, fb2, gffn, 2*ROWS, D, 2*D, 0);
  residual_ln_kernel<<<2*ROWS, 256>>>(out, gffn, g3, b3, out);
}

// round 5
// speedup vs baseline: 5.0414x; 1.2283x over previous
#include <cuda_runtime.h>
#include <cuda_bf16.h>
#include <math.h>
#include <stddef.h>
#include <stdint.h>

#define D 512
#define LSEQ 1024
#define BATCH 8
#define NH 8
#define HD 64
#define ROWS (BATCH*LSEQ)   /* 8192 */
#define BH (BATCH*NH)       /* 64   */
#define DD (D*D)

// ---------------- scratch (no allocations allowed) ----------------
__device__ __nv_bfloat16 g_x1b[ROWS*D];
__device__ __nv_bfloat16 g_x2b[ROWS*D];
__device__ __nv_bfloat16 g_qb[ROWS*D];
__device__ __nv_bfloat16 g_kvb[(size_t)ROWS*2*D];
__device__ __nv_bfloat16 g_ctxb[ROWS*D];
__device__ __nv_bfloat16 g_hidb[(size_t)2*ROWS*2*D];
__device__ __nv_bfloat16 g_xlnb[(size_t)2*ROWS*D];
__device__ __nv_bfloat16 g_wb[(size_t)12*DD];
__device__ float g_proj[ROWS*D];
__device__ float g_ffn[(size_t)2*ROWS*D];

// weight offsets in g_wb
#define WB_W1  0           /* win1: 3DD */
#define WB_WO1 (3*DD)      /* wout1: DD */
#define WB_W2  (4*DD)      /* win2: 3DD */
#define WB_WO2 (7*DD)      /* wout2: DD */
#define WB_F1  (8*DD)      /* fw1: 2DD  */
#define WB_F2  (10*DD)     /* fw2: 2DD  */

// ======================= helpers =======================
__device__ __forceinline__ uint32_t smem_u32(const void* p) {
  uint32_t a;
  asm("{ .reg .u64 t; cvta.to.shared.u64 t, %1; cvt.u32.u64 %0, t; }"
      : "=r"(a) : "l"(p));
  return a;
}

#define CP_ASYNC16(dst, src) \
  asm volatile("cp.async.cg.shared.global [%0], [%1], 16;" \
               :: "r"(dst), "l"(src))
#define CP_COMMIT() asm volatile("cp.async.commit_group;")
#define CP_WAIT(n)  asm volatile("cp.async.wait_group %0;" :: "n"(n))

#define LDSM_X4(r0, r1, r2, r3, addr) \
  asm volatile("ldmatrix.sync.aligned.m8n8.x4.shared.b16 {%0,%1,%2,%3}, [%4];" \
               : "=r"(r0), "=r"(r1), "=r"(r2), "=r"(r3) : "r"(addr))
#define LDSM_X4_T(r0, r1, r2, r3, addr) \
  asm volatile("ldmatrix.sync.aligned.m8n8.x4.trans.shared.b16 {%0,%1,%2,%3}, [%4];" \
               : "=r"(r0), "=r"(r1), "=r"(r2), "=r"(r3) : "r"(addr))

#define MMA_BF16(c, a, b) \
  asm volatile( \
    "mma.sync.aligned.m16n8k16.row.col.f32.bf16.bf16.f32 " \
    "{%0,%1,%2,%3}, {%4,%5,%6,%7}, {%8,%9}, {%0,%1,%2,%3};" \
    : "+f"((c)[0]), "+f"((c)[1]), "+f"((c)[2]), "+f"((c)[3]) \
    : "r"((a)[0]), "r"((a)[1]), "r"((a)[2]), "r"((a)[3]), \
      "r"((b)[0]), "r"((b)[1]))

// ---------------- fp32 -> bf16 convert (n multiple of 4) ----------------
__global__ void __launch_bounds__(256) f2bf(
    const float* __restrict__ x, __nv_bfloat16* __restrict__ y)
{
  int i = blockIdx.x * 256 + threadIdx.x;
  float4 v = ((const float4*)x)[i];
  __nv_bfloat162 a = __floats2bfloat162_rn(v.x, v.y);
  __nv_bfloat162 b = __floats2bfloat162_rn(v.z, v.w);
  ((uint2*)y)[i] = make_uint2(*(uint32_t*)&a, *(uint32_t*)&b);
}

// ======================= bf16 GEMM, cp.async 4-stage pipeline =============
// C = A[M,K] @ B[N,K]^T + bias; A,B bf16; outputs: Cf (fp32, opt), Cb (bf16, opt).
// Tiles 128x128x32. 8 warps 4(M)x2(N).
__global__ void __launch_bounds__(256) gemm_bf16(
    const __nv_bfloat16* __restrict__ A, const __nv_bfloat16* __restrict__ B,
    const float* __restrict__ bias, float* __restrict__ Cf,
    __nv_bfloat16* __restrict__ Cb,
    int nslab, int lda, int ldb, int ldc, int relu)
{
  __shared__ __align__(16) __nv_bfloat16 As[4][128][40];
  __shared__ __align__(16) __nv_bfloat16 Bs[4][128][40];

  const int tid = threadIdx.x;
  const int wid = tid >> 5, l = tid & 31;
  const int warp_m = wid & 3, warp_n = wid >> 2;

  const int bm = blockIdx.y * 128;
  const int bn = blockIdx.x * 128;

  float acc[2][8][4];
  #pragma unroll
  for (int i = 0; i < 2; i++)
    #pragma unroll
    for (int j = 0; j < 8; j++)
      #pragma unroll
      for (int k = 0; k < 4; k++) acc[i][j][k] = 0.f;

  auto issue = [&](int slab, int stg) {
    const int k0 = slab << 5;
    #pragma unroll
    for (int it = 0; it < 2; ++it) {
      int idx = tid + it * 256;
      int r = idx >> 2, c = (idx & 3) << 3;
      CP_ASYNC16(smem_u32(&As[stg][r][c]),
                 A + (size_t)(bm + r) * lda + k0 + c);
    }
    #pragma unroll
    for (int it = 0; it < 2; ++it) {
      int idx = tid + it * 256;
      int r = idx >> 2, c = (idx & 3) << 3;
      CP_ASYNC16(smem_u32(&Bs[stg][r][c]),
                 B + (size_t)(bn + r) * ldb + k0 + c);
    }
    CP_COMMIT();
  };

  #pragma unroll
  for (int s = 0; s < 3; s++) {
    if (s < nslab) issue(s, s); else CP_COMMIT();
  }

  for (int i = 0; i < nslab; i++) {
    CP_WAIT(2);
    __syncthreads();
    const int buf = i & 3;
    if (i + 3 < nslab) issue(i + 3, (i + 3) & 3); else CP_COMMIT();

    const uint32_t a_base = smem_u32(&As[buf][0][0]);
    const uint32_t b_base = smem_u32(&Bs[buf][0][0]);
    #pragma unroll
    for (int ks = 0; ks < 2; ks++) {
      const int k0 = ks * 16;
      uint32_t afr[2][4];
      #pragma unroll
      for (int mf = 0; mf < 2; mf++) {
        int row = warp_m * 32 + mf * 16 + (l & 15);
        uint32_t addr = a_base + (uint32_t)(row * 80 + (k0 + ((l >> 4) << 3)) * 2);
        LDSM_X4(afr[mf][0], afr[mf][1], afr[mf][2], afr[mf][3], addr);
      }
      uint32_t bfr[8][2];
      #pragma unroll
      for (int nf = 0; nf < 8; nf += 2) {
        int row = warp_n * 64 + nf * 8 + ((l >> 4) << 3) + (l & 7);
        int col = k0 + ((l >> 3) & 1) * 8;
        uint32_t addr = b_base + (uint32_t)(row * 80 + col * 2);
        LDSM_X4(bfr[nf][0], bfr[nf][1], bfr[nf + 1][0], bfr[nf + 1][1], addr);
      }
      #pragma unroll
      for (int mf = 0; mf < 2; mf++)
        #pragma unroll
        for (int nf = 0; nf < 8; nf++)
          MMA_BF16(acc[mf][nf], afr[mf], bfr[nf]);
    }
  }

  const int gid = l >> 2, tig = l & 3;
  #pragma unroll
  for (int mf = 0; mf < 2; mf++) {
    const int row = bm + warp_m * 32 + mf * 16 + gid;
    #pragma unroll
    for (int nf = 0; nf < 8; nf++) {
      const int col = bn + warp_n * 64 + nf * 8 + tig * 2;
      float2 bv = make_float2(0.f, 0.f);
      if (bias) bv = *(const float2*)(bias + col);
      float2 v0, v1;
      v0.x = acc[mf][nf][0] + bv.x;
      v0.y = acc[mf][nf][1] + bv.y;
      v1.x = acc[mf][nf][2] + bv.x;
      v1.y = acc[mf][nf][3] + bv.y;
      if (relu) {
        v0.x = fmaxf(v0.x, 0.f); v0.y = fmaxf(v0.y, 0.f);
        v1.x = fmaxf(v1.x, 0.f); v1.y = fmaxf(v1.y, 0.f);
      }
      if (Cf) {
        *(float2*)(Cf + (size_t)row * ldc + col) = v0;
        *(float2*)(Cf + (size_t)(row + 8) * ldc + col) = v1;
      }
      if (Cb) {
        __nv_bfloat162 h0 = __floats2bfloat162_rn(v0.x, v0.y);
        __nv_bfloat162 h1 = __floats2bfloat162_rn(v1.x, v1.y);
        *(uint32_t*)(Cb + (size_t)row * ldc + col) = *(uint32_t*)&h0;
        *(uint32_t*)(Cb + (size_t)(row + 8) * ldc + col) = *(uint32_t*)&h1;
      }
    }
  }
}

// ======================= fused attention (bf16 in, cp.async) ==============
// SMEM byte offsets
#define FA_QS   0
#define FA_KS   18432              /* double buffer: 2 x 128 x 72 bf16 */
#define FA_VS   55296
#define FA_PS   73728              /* 128 x 136 bf16 */
#define FA_ZS   108544
#define FA_SMEM 109056
#define FA_KSTRIDE 18432

__global__ void __launch_bounds__(256) fused_attn(
    const __nv_bfloat16* __restrict__ Q, const __nv_bfloat16* __restrict__ KV,
    float* __restrict__ attn, __nv_bfloat16* __restrict__ ctxb)
{
  extern __shared__ char sm[];
  __nv_bfloat16* Qs = (__nv_bfloat16*)(sm + FA_QS);   // [128][72]
  __nv_bfloat16* Ks = (__nv_bfloat16*)(sm + FA_KS);   // [2][128][72]
  __nv_bfloat16* Vs = (__nv_bfloat16*)(sm + FA_VS);   // [128][72]
  __nv_bfloat16* Ps = (__nv_bfloat16*)(sm + FA_PS);   // [128][136]
  float*         Zs = (float*)(sm + FA_ZS);           // [128]

  const int tid = threadIdx.x;
  const int wid = tid >> 5, l = tid & 31;
  const int warp_m = wid & 3, warp_n = wid >> 2;
  const int gid = l >> 2, tig = l & 3;

  const int z = blockIdx.y;
  const int b = z >> 3, h = z & 7;
  const int l0 = blockIdx.x * 128;

  const __nv_bfloat16* Qg = Q  + (size_t)b * LSEQ * D + h * HD;     // stride D
  const __nv_bfloat16* Kg = KV + (size_t)b * LSEQ * 2 * D + h * HD; // stride 2D
  const __nv_bfloat16* Vg = Kg + D;
  float* Pg = attn + (size_t)z * LSEQ * LSEQ;
  __nv_bfloat16* Ogb = ctxb + (size_t)b * LSEQ * D + h * HD;

  const uint32_t qsb = smem_u32(Qs);
  const uint32_t ks0 = smem_u32(Ks);
  const uint32_t vsb = smem_u32(Vs);
  const uint32_t psb = smem_u32(Ps);

  auto issue_q = [&]() {
    #pragma unroll
    for (int it = 0; it < 4; ++it) {
      int idx = tid + it * 256;
      int r = idx >> 3, c = (idx & 7) << 3;
      CP_ASYNC16(qsb + (uint32_t)(r * 144 + c * 2),
                 Qg + (size_t)(l0 + r) * D + c);
    }
    CP_COMMIT();
  };
  auto issue_k = [&](int s0, int kb) {
    const uint32_t base = ks0 + kb * FA_KSTRIDE;
    #pragma unroll
    for (int it = 0; it < 4; ++it) {
      int idx = tid + it * 256;
      int r = idx >> 3, c = (idx & 7) << 3;
      CP_ASYNC16(base + (uint32_t)(r * 144 + c * 2),
                 Kg + (size_t)(s0 + r) * 2 * D + c);
    }
    CP_COMMIT();
  };
  auto issue_v = [&](int s0) {
    #pragma unroll
    for (int it = 0; it < 4; ++it) {
      int idx = tid + it * 256;
      int r = idx >> 3, c = (idx & 7) << 3;
      CP_ASYNC16(vsb + (uint32_t)(r * 144 + c * 2),
                 Vg + (size_t)(s0 + r) * 2 * D + c);
    }
    CP_COMMIT();
  };

  if (tid < 128) Zs[tid] = 0.f;
  issue_q();
  issue_k(0, 0);

  // S = Q @ K^T (no scale), from Ks buffer kb
  auto s_mma = [&](float (*acc)[8][4], int kb) {
    const uint32_t ksb = ks0 + kb * FA_KSTRIDE;
    #pragma unroll
    for (int i = 0; i < 2; i++)
      #pragma unroll
      for (int j = 0; j < 8; j++)
        #pragma unroll
        for (int k = 0; k < 4; k++) acc[i][j][k] = 0.f;
    #pragma unroll
    for (int ks = 0; ks < 4; ks++) {
      const int k0 = ks * 16;
      uint32_t afr[2][4];
      #pragma unroll
      for (int mf = 0; mf < 2; mf++) {
        int row = warp_m * 32 + mf * 16 + (l & 15);
        uint32_t addr = qsb + (uint32_t)(row * 144 + (k0 + ((l >> 4) << 3)) * 2);
        LDSM_X4(afr[mf][0], afr[mf][1], afr[mf][2], afr[mf][3], addr);
      }
      uint32_t bfr[8][2];
      #pragma unroll
      for (int nf = 0; nf < 8; nf += 2) {
        int row = warp_n * 64 + nf * 8 + ((l >> 4) << 3) + (l & 7);
        int col = k0 + ((l >> 3) & 1) * 8;
        uint32_t addr = ksb + (uint32_t)(row * 144 + col * 2);
        LDSM_X4(bfr[nf][0], bfr[nf][1], bfr[nf + 1][0], bfr[nf + 1][1], addr);
      }
      #pragma unroll
      for (int mf = 0; mf < 2; mf++)
        #pragma unroll
        for (int nf = 0; nf < 8; nf++)
          MMA_BF16(acc[mf][nf], afr[mf], bfr[nf]);
    }
  };

  // ================= pass 1: row sums =================
  {
    float zr[2][2] = {{0.f, 0.f}, {0.f, 0.f}};
    for (int st = 0; st < 8; st++) {
      const int kb = st & 1;
      CP_WAIT(0);
      __syncthreads();
      if (st < 7) issue_k((st + 1) * 128, kb ^ 1); else CP_COMMIT();
      float acc[2][8][4];
      s_mma(acc, kb);
      #pragma unroll
      for (int mf = 0; mf < 2; mf++)
        #pragma unroll
        for (int nf = 0; nf < 8; nf++) {
          zr[mf][0] += __expf(acc[mf][nf][0] * 0.125f) + __expf(acc[mf][nf][1] * 0.125f);
          zr[mf][1] += __expf(acc[mf][nf][2] * 0.125f) + __expf(acc[mf][nf][3] * 0.125f);
        }
    }
    #pragma unroll
    for (int mf = 0; mf < 2; mf++)
      #pragma unroll
      for (int rp = 0; rp < 2; rp++) {
        float v = zr[mf][rp];
        v += __shfl_xor_sync(0xffffffffu, v, 1);
        v += __shfl_xor_sync(0xffffffffu, v, 2);
        if (tig == 0)
          atomicAdd(&Zs[warp_m * 32 + mf * 16 + rp * 8 + gid], v);
      }
    __syncthreads();
    if (tid < 128) Zs[tid] = 1.f / Zs[tid];
    // pass-2 prologue loads overlap the Z reduction epilogue
    issue_k(0, 0);
    issue_v(0);
    __syncthreads();
  }

  float iz[2][2];
  #pragma unroll
  for (int mf = 0; mf < 2; mf++)
    #pragma unroll
    for (int rp = 0; rp < 2; rp++)
      iz[mf][rp] = Zs[warp_m * 32 + mf * 16 + rp * 8 + gid];

  // ================= pass 2: write P, accumulate O = P@V =================
  float oacc[2][4][4];
  #pragma unroll
  for (int i = 0; i < 2; i++)
    #pragma unroll
    for (int j = 0; j < 4; j++)
      #pragma unroll
      for (int k = 0; k < 4; k++) oacc[i][j][k] = 0.f;

  for (int st = 0; st < 8; st++) {
    const int s0 = st * 128;
    const int kb = st & 1;
    CP_WAIT(1);                 // K(st) ready (V(st) may still be in flight)
    __syncthreads();
    if (st < 7) issue_k(s0 + 128, kb ^ 1); else CP_COMMIT();

    float acc[2][8][4];
    s_mma(acc, kb);

    // P = exp(S/8) * invZ : fp32 -> gmem, bf16 -> Ps
    #pragma unroll
    for (int mf = 0; mf < 2; mf++) {
      const int r0 = warp_m * 32 + mf * 16 + gid;
      #pragma unroll
      for (int nf = 0; nf < 8; nf++) {
        const int c = warp_n * 64 + nf * 8 + tig * 2;
        float p00 = __expf(acc[mf][nf][0] * 0.125f) * iz[mf][0];
        float p01 = __expf(acc[mf][nf][1] * 0.125f) * iz[mf][0];
        float p10 = __expf(acc[mf][nf][2] * 0.125f) * iz[mf][1];
        float p11 = __expf(acc[mf][nf][3] * 0.125f) * iz[mf][1];
        *(float2*)(Pg + (size_t)(l0 + r0) * LSEQ + s0 + c) = make_float2(p00, p01);
        *(float2*)(Pg + (size_t)(l0 + r0 + 8) * LSEQ + s0 + c) = make_float2(p10, p11);
        __nv_bfloat162 q0 = __floats2bfloat162_rn(p00, p01);
        __nv_bfloat162 q1 = __floats2bfloat162_rn(p10, p11);
        *(uint32_t*)&Ps[r0 * 136 + c] = *(uint32_t*)&q0;
        *(uint32_t*)&Ps[(r0 + 8) * 136 + c] = *(uint32_t*)&q1;
      }
    }
    CP_WAIT(1);                 // V(st) ready (K(st+1) may still be in flight)
    __syncthreads();            // Ps + Vs visible to all

    // O += P @ V
    #pragma unroll
    for (int ks = 0; ks < 8; ks++) {
      const int k0 = ks * 16;
      uint32_t afr[2][4];
      #pragma unroll
      for (int mf = 0; mf < 2; mf++) {
        int row = warp_m * 32 + mf * 16 + (l & 15);
        uint32_t addr = psb + (uint32_t)(row * 272 + (k0 + ((l >> 4) << 3)) * 2);
        LDSM_X4(afr[mf][0], afr[mf][1], afr[mf][2], afr[mf][3], addr);
      }
      uint32_t bfr[4][2];
      #pragma unroll
      for (int nf = 0; nf < 4; nf += 2) {
        int krow = k0 + ((l >> 3) & 1) * 8 + (l & 7);
        int ncol = warp_n * 32 + nf * 8 + ((l >> 4) << 3);
        uint32_t addr = vsb + (uint32_t)(krow * 144 + ncol * 2);
        LDSM_X4_T(bfr[nf][0], bfr[nf][1], bfr[nf + 1][0], bfr[nf + 1][1], addr);
      }
      #pragma unroll
      for (int mf = 0; mf < 2; mf++)
        #pragma unroll
        for (int nf = 0; nf < 4; nf++)
          MMA_BF16(oacc[mf][nf], afr[mf], bfr[nf]);
    }
    __syncthreads();            // all done reading Vs/Ps
    if (st < 7) issue_v(s0 + 128); else CP_COMMIT();
  }
  CP_WAIT(0);

  // ---- write ctx (bf16) ----
  #pragma unroll
  for (int mf = 0; mf < 2; mf++) {
    const int r0 = l0 + warp_m * 32 + mf * 16 + gid;
    #pragma unroll
    for (int nf = 0; nf < 4; nf++) {
      const int c = warp_n * 32 + nf * 8 + tig * 2;
      __nv_bfloat162 h0 = __floats2bfloat162_rn(oacc[mf][nf][0], oacc[mf][nf][1]);
      __nv_bfloat162 h1 = __floats2bfloat162_rn(oacc[mf][nf][2], oacc[mf][nf][3]);
      *(uint32_t*)(Ogb + (size_t)r0 * D + c) = *(uint32_t*)&h0;
      *(uint32_t*)(Ogb + (size_t)(r0 + 8) * D + c) = *(uint32_t*)&h1;
    }
  }
}

// ---------------- out = LN(x + y) * g + b, rows of 512 ----------------
__global__ void __launch_bounds__(256) residual_ln_kernel(
    const float* __restrict__ x, const float* __restrict__ y,
    const float* __restrict__ g, const float* __restrict__ b,
    float* __restrict__ out, __nv_bfloat16* __restrict__ outb)
{
  __shared__ float shs[8], shq[8];
  const size_t row = blockIdx.x;
  const int t = threadIdx.x;
  float2 xa = ((const float2*)x)[row * 256 + t];
  float2 ya = ((const float2*)y)[row * 256 + t];
  float v0 = xa.x + ya.x, v1 = xa.y + ya.y;
  float s = v0 + v1, q = v0*v0 + v1*v1;
  #pragma unroll
  for (int o = 16; o > 0; o >>= 1) {
    s += __shfl_xor_sync(0xffffffffu, s, o);
    q += __shfl_xor_sync(0xffffffffu, q, o);
  }
  if ((t & 31) == 0) { shs[t >> 5] = s; shq[t >> 5] = q; }
  __syncthreads();
  s = 0.f; q = 0.f;
  #pragma unroll
  for (int i = 0; i < 8; i++) { s += shs[i]; q += shq[i]; }
  float mu  = s * (1.f / 512.f);
  float var = q * (1.f / 512.f) - mu * mu;
  float inv = rsqrtf(var + 1e-5f);
  float2 gg = ((const float2*)g)[t];
  float2 bb = ((const float2*)b)[t];
  float2 o2;
  o2.x = (v0 - mu) * inv * gg.x + bb.x;
  o2.y = (v1 - mu) * inv * gg.y + bb.y;
  ((float2*)out)[row * 256 + t] = o2;
  if (outb) {
    __nv_bfloat162 h = __floats2bfloat162_rn(o2.x, o2.y);
    ((uint32_t*)outb)[row * 256 + t] = *(uint32_t*)&h;
  }
}

// ---------------- host-side orchestration ----------------
extern "C" void kernel_launch(void* const* d_in, const int* in_sizes, int n_in,
                              void* d_out, int out_size)
{
  const float* x1    = (const float*)d_in[0];
  const float* x2    = (const float*)d_in[1];
  const float* win1  = (const float*)d_in[2];
  const float* bin1  = (const float*)d_in[3];
  const float* wout1 = (const float*)d_in[4];
  const float* bout1 = (const float*)d_in[5];
  const float* win2  = (const float*)d_in[6];
  const float* bin2  = (const float*)d_in[7];
  const float* wout2 = (const float*)d_in[8];
  const float* bout2 = (const float*)d_in[9];
  const float* g1    = (const float*)d_in[10];
  const float* b1    = (const float*)d_in[11];
  const float* g2    = (const float*)d_in[12];
  const float* b2    = (const float*)d_in[13];
  const float* fw1   = (const float*)d_in[14];
  const float* fb1   = (const float*)d_in[15];
  const float* fw2   = (const float*)d_in[16];
  const float* fb2   = (const float*)d_in[17];
  const float* g3    = (const float*)d_in[18];
  const float* b3    = (const float*)d_in[19];

  cudaFuncSetAttribute(fused_attn, cudaFuncAttributeMaxDynamicSharedMemorySize, FA_SMEM);

  float* out = (float*)d_out;
  float* ox1 = out;
  float* ox2 = out + (size_t)ROWS * D;
  float* w12 = out + (size_t)2 * ROWS * D;
  float* w21 = w12 + (size_t)BH * LSEQ * LSEQ;

  __nv_bfloat16 *x1b, *x2b, *qb, *kvb, *ctxb, *hidb, *xlnb, *wb;
  float *proj, *ffn;
  cudaGetSymbolAddress((void**)&x1b,  g_x1b);
  cudaGetSymbolAddress((void**)&x2b,  g_x2b);
  cudaGetSymbolAddress((void**)&qb,   g_qb);
  cudaGetSymbolAddress((void**)&kvb,  g_kvb);
  cudaGetSymbolAddress((void**)&ctxb, g_ctxb);
  cudaGetSymbolAddress((void**)&hidb, g_hidb);
  cudaGetSymbolAddress((void**)&xlnb, g_xlnb);
  cudaGetSymbolAddress((void**)&wb,   g_wb);
  cudaGetSymbolAddress((void**)&proj, g_proj);
  cudaGetSymbolAddress((void**)&ffn,  g_ffn);

  // ---- converts (once per value; rounding identical to R4 path) ----
  f2bf<<<ROWS*D/1024, 256>>>(x1, x1b);
  f2bf<<<ROWS*D/1024, 256>>>(x2, x2b);
  f2bf<<<3*DD/1024, 256>>>(win1,  wb + WB_W1);
  f2bf<<<DD/1024,   256>>>(wout1, wb + WB_WO1);
  f2bf<<<3*DD/1024, 256>>>(win2,  wb + WB_W2);
  f2bf<<<DD/1024,   256>>>(wout2, wb + WB_WO2);
  f2bf<<<2*DD/1024, 256>>>(fw1,   wb + WB_F1);
  f2bf<<<2*DD/1024, 256>>>(fw2,   wb + WB_F2);

  // ---- mha1: q from x1, kv from x2 ----
  gemm_bf16<<<dim3(4, 64), 256>>>(x1b, wb + WB_W1, bin1, nullptr, qb,
                                  16, D, D, D, 0);
  gemm_bf16<<<dim3(8, 64), 256>>>(x2b, wb + WB_W1 + DD, bin1 + D, nullptr, kvb,
                                  16, D, D, 2*D, 0);
  fused_attn<<<dim3(8, BH), 256, FA_SMEM>>>(qb, kvb, w12, ctxb);
  gemm_bf16<<<dim3(4, 64), 256>>>(ctxb, wb + WB_WO1, bout1, proj, nullptr,
                                  16, D, D, D, 0);
  residual_ln_kernel<<<ROWS, 256>>>(x1, proj, g1, b1, ox1, xlnb);

  // ---- mha2: q from x2, kv from x1_a ----
  gemm_bf16<<<dim3(4, 64), 256>>>(x2b, wb + WB_W2, bin2, nullptr, qb,
                                  16, D, D, D, 0);
  gemm_bf16<<<dim3(8, 64), 256>>>(xlnb, wb + WB_W2 + DD, bin2 + D, nullptr, kvb,
                                  16, D, D, 2*D, 0);
  fused_attn<<<dim3(8, BH), 256, FA_SMEM>>>(qb, kvb, w21, ctxb);
  gemm_bf16<<<dim3(4, 64), 256>>>(ctxb, wb + WB_WO2, bout2, proj, nullptr,
                                  16, D, D, D, 0);
  residual_ln_kernel<<<ROWS, 256>>>(x2, proj, g2, b2, ox2, xlnb + (size_t)ROWS * D);

  // ---- FFN over both streams: [x1_a; x2_a] bf16 contiguous (16384, 512) ----
  gemm_bf16<<<dim3(8, 128), 256>>>(xlnb, wb + WB_F1, fb1, nullptr, hidb,
                                   16, D, D, 2*D, 1);
  gemm_bf16<<<dim3(4, 128), 256>>>(hidb, wb + WB_F2, fb2, ffn, nullptr,
                                   32, 2*D, 2*D, D, 0);
  residual_ln_kernel<<<2*ROWS, 256>>>(out, ffn, g3, b3, out, nullptr);
}

// round 6
// speedup vs baseline: 5.5028x; 1.0915x over previous
#include <cuda_runtime.h>
#include <cuda_bf16.h>
#include <math.h>
#include <stddef.h>
#include <stdint.h>

#define D 512
#define LSEQ 1024
#define BATCH 8
#define NH 8
#define HD 64
#define ROWS (BATCH*LSEQ)   /* 8192 */
#define BH (BATCH*NH)       /* 64   */
#define DD (D*D)

// ---------------- scratch (no allocations allowed) ----------------
__device__ __nv_bfloat16 g_x1b[ROWS*D];
__device__ __nv_bfloat16 g_x2b[ROWS*D];
__device__ __nv_bfloat16 g_qb[ROWS*D];
__device__ __nv_bfloat16 g_kvb[(size_t)ROWS*2*D];
__device__ __nv_bfloat16 g_ctxb[ROWS*D];
__device__ __nv_bfloat16 g_hidb[(size_t)2*ROWS*2*D];
__device__ __nv_bfloat16 g_xlnb[(size_t)2*ROWS*D];
__device__ __nv_bfloat16 g_wb[(size_t)12*DD];
__device__ float g_proj[ROWS*D];
__device__ float g_ffn[(size_t)2*ROWS*D];

// weight offsets in g_wb
#define WB_W1  0           /* win1: 3DD */
#define WB_WO1 (3*DD)      /* wout1: DD */
#define WB_W2  (4*DD)      /* win2: 3DD */
#define WB_WO2 (7*DD)      /* wout2: DD */
#define WB_F1  (8*DD)      /* fw1: 2DD  */
#define WB_F2  (10*DD)     /* fw2: 2DD  */

// ======================= helpers =======================
__device__ __forceinline__ uint32_t smem_u32(const void* p) {
  uint32_t a;
  asm("{ .reg .u64 t; cvta.to.shared.u64 t, %1; cvt.u32.u64 %0, t; }"
      : "=r"(a) : "l"(p));
  return a;
}

#define CP_ASYNC16(dst, src) \
  asm volatile("cp.async.cg.shared.global [%0], [%1], 16;" \
               :: "r"(dst), "l"(src))
#define CP_COMMIT() asm volatile("cp.async.commit_group;")
#define CP_WAIT(n)  asm volatile("cp.async.wait_group %0;" :: "n"(n))

#define LDSM_X4(r0, r1, r2, r3, addr) \
  asm volatile("ldmatrix.sync.aligned.m8n8.x4.shared.b16 {%0,%1,%2,%3}, [%4];" \
               : "=r"(r0), "=r"(r1), "=r"(r2), "=r"(r3) : "r"(addr))
#define LDSM_X4_T(r0, r1, r2, r3, addr) \
  asm volatile("ldmatrix.sync.aligned.m8n8.x4.trans.shared.b16 {%0,%1,%2,%3}, [%4];" \
               : "=r"(r0), "=r"(r1), "=r"(r2), "=r"(r3) : "r"(addr))

#define MMA_BF16(c, a, b) \
  asm volatile( \
    "mma.sync.aligned.m16n8k16.row.col.f32.bf16.bf16.f32 " \
    "{%0,%1,%2,%3}, {%4,%5,%6,%7}, {%8,%9}, {%0,%1,%2,%3};" \
    : "+f"((c)[0]), "+f"((c)[1]), "+f"((c)[2]), "+f"((c)[3]) \
    : "r"((a)[0]), "r"((a)[1]), "r"((a)[2]), "r"((a)[3]), \
      "r"((b)[0]), "r"((b)[1]))

// ---------------- fp32 -> bf16 convert (n multiple of 4) ----------------
__global__ void __launch_bounds__(256) f2bf(
    const float* __restrict__ x, __nv_bfloat16* __restrict__ y)
{
  int i = blockIdx.x * 256 + threadIdx.x;
  float4 v = ((const float4*)x)[i];
  __nv_bfloat162 a = __floats2bfloat162_rn(v.x, v.y);
  __nv_bfloat162 b = __floats2bfloat162_rn(v.z, v.w);
  ((uint2*)y)[i] = make_uint2(*(uint32_t*)&a, *(uint32_t*)&b);
}

// ======================= bf16 GEMM, cp.async 4-stage pipeline =============
// C = A[M,K] @ B[N,K]^T + bias; A,B bf16; outputs: Cf (fp32, opt), Cb (bf16, opt).
// Tiles 128x128x32. 8 warps 4(M)x2(N).
__global__ void __launch_bounds__(256) gemm_bf16(
    const __nv_bfloat16* __restrict__ A, const __nv_bfloat16* __restrict__ B,
    const float* __restrict__ bias, float* __restrict__ Cf,
    __nv_bfloat16* __restrict__ Cb,
    int nslab, int lda, int ldb, int ldc, int relu)
{
  __shared__ __align__(16) __nv_bfloat16 As[4][128][40];
  __shared__ __align__(16) __nv_bfloat16 Bs[4][128][40];

  const int tid = threadIdx.x;
  const int wid = tid >> 5, l = tid & 31;
  const int warp_m = wid & 3, warp_n = wid >> 2;

  const int bm = blockIdx.y * 128;
  const int bn = blockIdx.x * 128;

  float acc[2][8][4];
  #pragma unroll
  for (int i = 0; i < 2; i++)
    #pragma unroll
    for (int j = 0; j < 8; j++)
      #pragma unroll
      for (int k = 0; k < 4; k++) acc[i][j][k] = 0.f;

  auto issue = [&](int slab, int stg) {
    const int k0 = slab << 5;
    #pragma unroll
    for (int it = 0; it < 2; ++it) {
      int idx = tid + it * 256;
      int r = idx >> 2, c = (idx & 3) << 3;
      CP_ASYNC16(smem_u32(&As[stg][r][c]),
                 A + (size_t)(bm + r) * lda + k0 + c);
    }
    #pragma unroll
    for (int it = 0; it < 2; ++it) {
      int idx = tid + it * 256;
      int r = idx >> 2, c = (idx & 3) << 3;
      CP_ASYNC16(smem_u32(&Bs[stg][r][c]),
                 B + (size_t)(bn + r) * ldb + k0 + c);
    }
    CP_COMMIT();
  };

  #pragma unroll
  for (int s = 0; s < 3; s++) {
    if (s < nslab) issue(s, s); else CP_COMMIT();
  }

  for (int i = 0; i < nslab; i++) {
    CP_WAIT(2);
    __syncthreads();
    const int buf = i & 3;
    if (i + 3 < nslab) issue(i + 3, (i + 3) & 3); else CP_COMMIT();

    const uint32_t a_base = smem_u32(&As[buf][0][0]);
    const uint32_t b_base = smem_u32(&Bs[buf][0][0]);
    #pragma unroll
    for (int ks = 0; ks < 2; ks++) {
      const int k0 = ks * 16;
      uint32_t afr[2][4];
      #pragma unroll
      for (int mf = 0; mf < 2; mf++) {
        int row = warp_m * 32 + mf * 16 + (l & 15);
        uint32_t addr = a_base + (uint32_t)(row * 80 + (k0 + ((l >> 4) << 3)) * 2);
        LDSM_X4(afr[mf][0], afr[mf][1], afr[mf][2], afr[mf][3], addr);
      }
      uint32_t bfr[8][2];
      #pragma unroll
      for (int nf = 0; nf < 8; nf += 2) {
        int row = warp_n * 64 + nf * 8 + ((l >> 4) << 3) + (l & 7);
        int col = k0 + ((l >> 3) & 1) * 8;
        uint32_t addr = b_base + (uint32_t)(row * 80 + col * 2);
        LDSM_X4(bfr[nf][0], bfr[nf][1], bfr[nf + 1][0], bfr[nf + 1][1], addr);
      }
      #pragma unroll
      for (int mf = 0; mf < 2; mf++)
        #pragma unroll
        for (int nf = 0; nf < 8; nf++)
          MMA_BF16(acc[mf][nf], afr[mf], bfr[nf]);
    }
  }

  const int gid = l >> 2, tig = l & 3;
  #pragma unroll
  for (int mf = 0; mf < 2; mf++) {
    const int row = bm + warp_m * 32 + mf * 16 + gid;
    #pragma unroll
    for (int nf = 0; nf < 8; nf++) {
      const int col = bn + warp_n * 64 + nf * 8 + tig * 2;
      float2 bv = make_float2(0.f, 0.f);
      if (bias) bv = *(const float2*)(bias + col);
      float2 v0, v1;
      v0.x = acc[mf][nf][0] + bv.x;
      v0.y = acc[mf][nf][1] + bv.y;
      v1.x = acc[mf][nf][2] + bv.x;
      v1.y = acc[mf][nf][3] + bv.y;
      if (relu) {
        v0.x = fmaxf(v0.x, 0.f); v0.y = fmaxf(v0.y, 0.f);
        v1.x = fmaxf(v1.x, 0.f); v1.y = fmaxf(v1.y, 0.f);
      }
      if (Cf) {
        *(float2*)(Cf + (size_t)row * ldc + col) = v0;
        *(float2*)(Cf + (size_t)(row + 8) * ldc + col) = v1;
      }
      if (Cb) {
        __nv_bfloat162 h0 = __floats2bfloat162_rn(v0.x, v0.y);
        __nv_bfloat162 h1 = __floats2bfloat162_rn(v1.x, v1.y);
        *(uint32_t*)(Cb + (size_t)row * ldc + col) = *(uint32_t*)&h0;
        *(uint32_t*)(Cb + (size_t)(row + 8) * ldc + col) = *(uint32_t*)&h1;
      }
    }
  }
}

// ======================= fused attention v2 ================================
// 8 warps, each owns 16 q-rows and the FULL 128 S-columns of a tile.
// P stays in registers (acc -> A-frag identity); no P smem round-trip.
// SMEM: Qs 18432 | Ks 2x18432 | Vs 18432 | Zs 512  => 74240 B -> 2 CTA/SM.
#define FA_QS   0
#define FA_KS   18432
#define FA_VS   55296
#define FA_ZS   73728
#define FA_SMEM 74240
#define FA_KSTRIDE 18432

__global__ void __launch_bounds__(256, 2) fused_attn(
    const __nv_bfloat16* __restrict__ Q, const __nv_bfloat16* __restrict__ KV,
    float* __restrict__ attn, __nv_bfloat16* __restrict__ ctxb)
{
  extern __shared__ char sm[];
  __nv_bfloat16* Qs = (__nv_bfloat16*)(sm + FA_QS);   // [128][72]
  float*         Zs = (float*)(sm + FA_ZS);           // [128]

  const int tid = threadIdx.x;
  const int wid = tid >> 5, l = tid & 31;
  const int gid = l >> 2, tig = l & 3;

  const int z = blockIdx.y;
  const int b = z >> 3, h = z & 7;
  const int l0 = blockIdx.x * 128;

  const __nv_bfloat16* Qg = Q  + (size_t)b * LSEQ * D + h * HD;     // stride D
  const __nv_bfloat16* Kg = KV + (size_t)b * LSEQ * 2 * D + h * HD; // stride 2D
  const __nv_bfloat16* Vg = Kg + D;
  float* Pg = attn + (size_t)z * LSEQ * LSEQ;
  __nv_bfloat16* Ogb = ctxb + (size_t)b * LSEQ * D + h * HD;

  const uint32_t qsb = smem_u32(sm + FA_QS);
  const uint32_t ks0 = smem_u32(sm + FA_KS);
  const uint32_t vsb = smem_u32(sm + FA_VS);

  auto issue_q = [&]() {
    #pragma unroll
    for (int it = 0; it < 4; ++it) {
      int idx = tid + it * 256;
      int r = idx >> 3, c = (idx & 7) << 3;
      CP_ASYNC16(qsb + (uint32_t)(r * 144 + c * 2),
                 Qg + (size_t)(l0 + r) * D + c);
    }
    CP_COMMIT();
  };
  auto issue_k = [&](int s0, int kb) {
    const uint32_t base = ks0 + kb * FA_KSTRIDE;
    #pragma unroll
    for (int it = 0; it < 4; ++it) {
      int idx = tid + it * 256;
      int r = idx >> 3, c = (idx & 7) << 3;
      CP_ASYNC16(base + (uint32_t)(r * 144 + c * 2),
                 Kg + (size_t)(s0 + r) * 2 * D + c);
    }
    CP_COMMIT();
  };
  auto issue_v = [&](int s0) {
    #pragma unroll
    for (int it = 0; it < 4; ++it) {
      int idx = tid + it * 256;
      int r = idx >> 3, c = (idx & 7) << 3;
      CP_ASYNC16(vsb + (uint32_t)(r * 144 + c * 2),
                 Vg + (size_t)(s0 + r) * 2 * D + c);
    }
    CP_COMMIT();
  };

  issue_q();
  issue_k(0, 0);

  // S half: acc[8][4] covers n-cols [half*64, half*64+64) for this warp's 16 rows
  auto s_half = [&](float (*acc)[4], int kb, int half) {
    const uint32_t ksb = ks0 + kb * FA_KSTRIDE;
    #pragma unroll
    for (int j = 0; j < 8; j++)
      #pragma unroll
      for (int k = 0; k < 4; k++) acc[j][k] = 0.f;
    #pragma unroll
    for (int ks = 0; ks < 4; ks++) {
      const int k0 = ks * 16;
      uint32_t afr[4];
      {
        int row = wid * 16 + (l & 15);
        uint32_t addr = qsb + (uint32_t)(row * 144 + (k0 + ((l >> 4) << 3)) * 2);
        LDSM_X4(afr[0], afr[1], afr[2], afr[3], addr);
      }
      uint32_t bfr[8][2];
      #pragma unroll
      for (int nf = 0; nf < 8; nf += 2) {
        int row = half * 64 + nf * 8 + ((l >> 4) << 3) + (l & 7);
        int col = k0 + ((l >> 3) & 1) * 8;
        uint32_t addr = ksb + (uint32_t)(row * 144 + col * 2);
        LDSM_X4(bfr[nf][0], bfr[nf][1], bfr[nf + 1][0], bfr[nf + 1][1], addr);
      }
      #pragma unroll
      for (int nf = 0; nf < 8; nf++)
        MMA_BF16(acc[nf], afr, bfr[nf]);
    }
  };

  // ================= pass 1: row sums =================
  {
    float zr[2] = {0.f, 0.f};
    for (int st = 0; st < 8; st++) {
      const int kb = st & 1;
      CP_WAIT(0);
      __syncthreads();
      if (st < 7) issue_k((st + 1) * 128, kb ^ 1); else CP_COMMIT();
      #pragma unroll
      for (int half = 0; half < 2; half++) {
        float acc[8][4];
        s_half(acc, kb, half);
        #pragma unroll
        for (int nf = 0; nf < 8; nf++) {
          zr[0] += __expf(acc[nf][0] * 0.125f) + __expf(acc[nf][1] * 0.125f);
          zr[1] += __expf(acc[nf][2] * 0.125f) + __expf(acc[nf][3] * 0.125f);
        }
      }
    }
    #pragma unroll
    for (int rp = 0; rp < 2; rp++) {
      float v = zr[rp];
      v += __shfl_xor_sync(0xffffffffu, v, 1);
      v += __shfl_xor_sync(0xffffffffu, v, 2);
      if (tig == 0) Zs[wid * 16 + rp * 8 + gid] = v;
    }
    __syncthreads();
    if (tid < 128) Zs[tid] = 1.f / Zs[tid];
    issue_k(0, 0);
    issue_v(0);
    __syncthreads();
  }

  float iz[2];
  iz[0] = Zs[wid * 16 + gid];
  iz[1] = Zs[wid * 16 + 8 + gid];

  // ================= pass 2: write P, accumulate O = P@V =================
  float oacc[8][4];
  #pragma unroll
  for (int j = 0; j < 8; j++)
    #pragma unroll
    for (int k = 0; k < 4; k++) oacc[j][k] = 0.f;

  for (int st = 0; st < 8; st++) {
    const int s0 = st * 128;
    const int kb = st & 1;
    CP_WAIT(1);                 // K(st) ready (V(st) in flight)
    __syncthreads();
    if (st < 7) issue_k(s0 + 128, kb ^ 1); else CP_COMMIT();

    uint32_t pk[8][4];          // packed P A-frags: kk=0..7 covers S-cols kk*16..+15
    #pragma unroll
    for (int half = 0; half < 2; half++) {
      float acc[8][4];
      s_half(acc, kb, half);
      #pragma unroll
      for (int nf = 0; nf < 8; nf++) {
        const int gnf = half * 8 + nf;
        const int c = gnf * 8 + tig * 2;
        const int r0 = wid * 16 + gid;
        float p00 = __expf(acc[nf][0] * 0.125f) * iz[0];
        float p01 = __expf(acc[nf][1] * 0.125f) * iz[0];
        float p10 = __expf(acc[nf][2] * 0.125f) * iz[1];
        float p11 = __expf(acc[nf][3] * 0.125f) * iz[1];
        *(float2*)(Pg + (size_t)(l0 + r0) * LSEQ + s0 + c) = make_float2(p00, p01);
        *(float2*)(Pg + (size_t)(l0 + r0 + 8) * LSEQ + s0 + c) = make_float2(p10, p11);
        __nv_bfloat162 q0 = __floats2bfloat162_rn(p00, p01);
        __nv_bfloat162 q1 = __floats2bfloat162_rn(p10, p11);
        const int kk = gnf >> 1;
        if ((gnf & 1) == 0) {
          pk[kk][0] = *(uint32_t*)&q0;
          pk[kk][1] = *(uint32_t*)&q1;
        } else {
          pk[kk][2] = *(uint32_t*)&q0;
          pk[kk][3] = *(uint32_t*)&q1;
        }
      }
    }
    CP_WAIT(1);                 // V(st) ready (K(st+1) in flight)
    __syncthreads();

    // O += P @ V  (full k per warp; B = V^T via ldmatrix.trans)
    #pragma unroll
    for (int kk = 0; kk < 8; kk++) {
      uint32_t bfr[8][2];
      #pragma unroll
      for (int nf = 0; nf < 8; nf += 2) {
        int krow = kk * 16 + ((l >> 3) & 1) * 8 + (l & 7);
        int ncol = nf * 8 + ((l >> 4) << 3);
        uint32_t addr = vsb + (uint32_t)(krow * 144 + ncol * 2);
        LDSM_X4_T(bfr[nf][0], bfr[nf][1], bfr[nf + 1][0], bfr[nf + 1][1], addr);
      }
      #pragma unroll
      for (int nf = 0; nf < 8; nf++)
        MMA_BF16(oacc[nf], pk[kk], bfr[nf]);
    }
    __syncthreads();            // all warps done reading Vs
    if (st < 7) issue_v(s0 + 128); else CP_COMMIT();
  }
  CP_WAIT(0);

  // ---- write ctx (bf16) ----
  {
    const int r0 = l0 + wid * 16 + gid;
    #pragma unroll
    for (int nf = 0; nf < 8; nf++) {
      const int c = nf * 8 + tig * 2;
      __nv_bfloat162 h0 = __floats2bfloat162_rn(oacc[nf][0], oacc[nf][1]);
      __nv_bfloat162 h1 = __floats2bfloat162_rn(oacc[nf][2], oacc[nf][3]);
      *(uint32_t*)(Ogb + (size_t)r0 * D + c) = *(uint32_t*)&h0;
      *(uint32_t*)(Ogb + (size_t)(r0 + 8) * D + c) = *(uint32_t*)&h1;
    }
  }
}

// ---------------- out = LN(x + y) * g + b, rows of 512 ----------------
__global__ void __launch_bounds__(256) residual_ln_kernel(
    const float* __restrict__ x, const float* __restrict__ y,
    const float* __restrict__ g, const float* __restrict__ b,
    float* __restrict__ out, __nv_bfloat16* __restrict__ outb)
{
  __shared__ float shs[8], shq[8];
  const size_t row = blockIdx.x;
  const int t = threadIdx.x;
  float2 xa = ((const float2*)x)[row * 256 + t];
  float2 ya = ((const float2*)y)[row * 256 + t];
  float v0 = xa.x + ya.x, v1 = xa.y + ya.y;
  float s = v0 + v1, q = v0*v0 + v1*v1;
  #pragma unroll
  for (int o = 16; o > 0; o >>= 1) {
    s += __shfl_xor_sync(0xffffffffu, s, o);
    q += __shfl_xor_sync(0xffffffffu, q, o);
  }
  if ((t & 31) == 0) { shs[t >> 5] = s; shq[t >> 5] = q; }
  __syncthreads();
  s = 0.f; q = 0.f;
  #pragma unroll
  for (int i = 0; i < 8; i++) { s += shs[i]; q += shq[i]; }
  float mu  = s * (1.f / 512.f);
  float var = q * (1.f / 512.f) - mu * mu;
  float inv = rsqrtf(var + 1e-5f);
  float2 gg = ((const float2*)g)[t];
  float2 bb = ((const float2*)b)[t];
  float2 o2;
  o2.x = (v0 - mu) * inv * gg.x + bb.x;
  o2.y = (v1 - mu) * inv * gg.y + bb.y;
  ((float2*)out)[row * 256 + t] = o2;
  if (outb) {
    __nv_bfloat162 h = __floats2bfloat162_rn(o2.x, o2.y);
    ((uint32_t*)outb)[row * 256 + t] = *(uint32_t*)&h;
  }
}

// ---------------- host-side orchestration ----------------
extern "C" void kernel_launch(void* const* d_in, const int* in_sizes, int n_in,
                              void* d_out, int out_size)
{
  const float* x1    = (const float*)d_in[0];
  const float* x2    = (const float*)d_in[1];
  const float* win1  = (const float*)d_in[2];
  const float* bin1  = (const float*)d_in[3];
  const float* wout1 = (const float*)d_in[4];
  const float* bout1 = (const float*)d_in[5];
  const float* win2  = (const float*)d_in[6];
  const float* bin2  = (const float*)d_in[7];
  const float* wout2 = (const float*)d_in[8];
  const float* bout2 = (const float*)d_in[9];
  const float* g1    = (const float*)d_in[10];
  const float* b1    = (const float*)d_in[11];
  const float* g2    = (const float*)d_in[12];
  const float* b2    = (const float*)d_in[13];
  const float* fw1   = (const float*)d_in[14];
  const float* fb1   = (const float*)d_in[15];
  const float* fw2   = (const float*)d_in[16];
  const float* fb2   = (const float*)d_in[17];
  const float* g3    = (const float*)d_in[18];
  const float* b3    = (const float*)d_in[19];

  cudaFuncSetAttribute(fused_attn, cudaFuncAttributeMaxDynamicSharedMemorySize, FA_SMEM);

  float* out = (float*)d_out;
  float* ox1 = out;
  float* ox2 = out + (size_t)ROWS * D;
  float* w12 = out + (size_t)2 * ROWS * D;
  float* w21 = w12 + (size_t)BH * LSEQ * LSEQ;

  __nv_bfloat16 *x1b, *x2b, *qb, *kvb, *ctxb, *hidb, *xlnb, *wb;
  float *proj, *ffn;
  cudaGetSymbolAddress((void**)&x1b,  g_x1b);
  cudaGetSymbolAddress((void**)&x2b,  g_x2b);
  cudaGetSymbolAddress((void**)&qb,   g_qb);
  cudaGetSymbolAddress((void**)&kvb,  g_kvb);
  cudaGetSymbolAddress((void**)&ctxb, g_ctxb);
  cudaGetSymbolAddress((void**)&hidb, g_hidb);
  cudaGetSymbolAddress((void**)&xlnb, g_xlnb);
  cudaGetSymbolAddress((void**)&wb,   g_wb);
  cudaGetSymbolAddress((void**)&proj, g_proj);
  cudaGetSymbolAddress((void**)&ffn,  g_ffn);

  // Launch order arranged so fused_attn (mha1) is host-launch index 5 (ncu -s 5 -c 1).
  f2bf<<<ROWS*D/1024, 256>>>(x1, x1b);                                   // 0
  f2bf<<<ROWS*D/1024, 256>>>(x2, x2b);                                   // 1
  f2bf<<<3*DD/1024, 256>>>(win1,  wb + WB_W1);                           // 2
  gemm_bf16<<<dim3(4, 64), 256>>>(x1b, wb + WB_W1, bin1, nullptr, qb,    // 3
                                  16, D, D, D, 0);
  gemm_bf16<<<dim3(8, 64), 256>>>(x2b, wb + WB_W1 + DD, bin1 + D,        // 4
                                  nullptr, kvb, 16, D, D, 2*D, 0);
  fused_attn<<<dim3(8, BH), 256, FA_SMEM>>>(qb, kvb, w12, ctxb);         // 5  <- profiled
  f2bf<<<DD/1024,   256>>>(wout1, wb + WB_WO1);                          // 6
  gemm_bf16<<<dim3(4, 64), 256>>>(ctxb, wb + WB_WO1, bout1, proj,        // 7
                                  nullptr, 16, D, D, D, 0);
  residual_ln_kernel<<<ROWS, 256>>>(x1, proj, g1, b1, ox1, xlnb);        // 8

  f2bf<<<3*DD/1024, 256>>>(win2,  wb + WB_W2);                           // 9
  gemm_bf16<<<dim3(4, 64), 256>>>(x2b, wb + WB_W2, bin2, nullptr, qb,    // 10
                                  16, D, D, D, 0);
  gemm_bf16<<<dim3(8, 64), 256>>>(xlnb, wb + WB_W2 + DD, bin2 + D,       // 11
                                  nullptr, kvb, 16, D, D, 2*D, 0);
  fused_attn<<<dim3(8, BH), 256, FA_SMEM>>>(qb, kvb, w21, ctxb);         // 12
  f2bf<<<DD/1024,   256>>>(wout2, wb + WB_WO2);                          // 13
  gemm_bf16<<<dim3(4, 64), 256>>>(ctxb, wb + WB_WO2, bout2, proj,        // 14
                                  nullptr, 16, D, D, D, 0);
  residual_ln_kernel<<<ROWS, 256>>>(x2, proj, g2, b2, ox2,               // 15
                                    xlnb + (size_t)ROWS * D);

  f2bf<<<2*DD/1024, 256>>>(fw1, wb + WB_F1);                             // 16
  f2bf<<<2*DD/1024, 256>>>(fw2, wb + WB_F2);                             // 17
  gemm_bf16<<<dim3(8, 128), 256>>>(xlnb, wb + WB_F1, fb1, nullptr, hidb, // 18
                                   16, D, D, 2*D, 1);
  gemm_bf16<<<dim3(4, 128), 256>>>(hidb, wb + WB_F2, fb2, ffn, nullptr,  // 19
                                   32, 2*D, 2*D, D, 0);
  residual_ln_kernel<<<2*ROWS, 256>>>(out, ffn, g3, b3, out, nullptr);   // 20
}